// round 11
// baseline (speedup 1.0000x reference)
#include <cuda_runtime.h>
#include <cuda_fp16.h>
#include <math.h>

// ---------------------------------------------------------------------------
// GIN (3 GINConv layers + BN + ReLU + MLP head)
//   N_NODES=100000, N_EDGES=1200000, D_IN=128, D_H=64, N_GRAPHS=256
// R10 changes vs R9 (454.7us):
//   * x transposed once into xt[128][N] (coalesced transpose kernel)
//   * gemmA rewritten: 4 nodes x 16 cols per thread; activation read is ONE
//     coalesced LDG.128 per k (1 wavefront) instead of strided row reads
//     (16 wavefronts/load). Weight LDS halved (4 instead of 8 per k).
//   * everything else byte-identical to R9.
// ---------------------------------------------------------------------------

#define MAX_NODES 100000
#define MAX_EDGES 1200000
#define NGRAPH    256
#define SCAN_B    1024
#define MAX_SCAN_BLOCKS 128

__device__ float g_z   [MAX_NODES * 64];          // fp32 aggregated rows
__device__ float g_xt  [128 * MAX_NODES + 128];   // transposed x (k-major) + pad
__device__ uint2 g_hh  [MAX_NODES * 16 + 16];     // fp16 activation rows + pad
__device__ float g_pool[NGRAPH * 192];
__device__ int   g_deg [MAX_NODES + 1];
__device__ int   g_row [MAX_NODES + 1];
__device__ int   g_cur [MAX_NODES];
__device__ int   g_col [MAX_EDGES];
__device__ int   g_bsum[MAX_SCAN_BLOCKS];

typedef unsigned long long ull;

__device__ __forceinline__ ull pack2(float lo, float hi) {
    ull r; asm("mov.b64 %0,{%1,%2};" : "=l"(r) : "f"(lo), "f"(hi)); return r;
}
__device__ __forceinline__ void unpack2(ull v, float& lo, float& hi) {
    asm("mov.b64 {%0,%1},%2;" : "=f"(lo), "=f"(hi) : "l"(v));
}
__device__ __forceinline__ ull fma2(ull a, ull b, ull c) {
    ull d; asm("fma.rn.f32x2 %0,%1,%2,%3;" : "=l"(d) : "l"(a), "l"(b), "l"(c)); return d;
}
__device__ __forceinline__ float4 h2f4(uint2 u) {
    __half2 a = *(__half2*)&u.x, b = *(__half2*)&u.y;
    float2 fa = __half22float2(a), fb = __half22float2(b);
    return make_float4(fa.x, fa.y, fb.x, fb.y);
}
__device__ __forceinline__ uint2 f4h(float a, float b, float c, float d) {
    __half2 lo = __floats2half2_rn(a, b), hi = __floats2half2_rn(c, d);
    uint2 u; u.x = *(unsigned*)&lo; u.y = *(unsigned*)&hi; return u;
}

// One k-step: one weight row segment (32 cols) feeds TWO nodes' accumulators.
__device__ __forceinline__ void fma_k32_dual(ull* accA, ull* accB,
                                             const float* ws, int k, int halfoff,
                                             float va, float vb) {
    ull a2 = pack2(va, va), b2 = pack2(vb, vb);
    const ulonglong2* wrow = (const ulonglong2*)(ws + k * 64 + halfoff);
#pragma unroll
    for (int j8 = 0; j8 < 8; j8++) {
        ulonglong2 wv = wrow[j8];
        accA[j8 * 2 + 0] = fma2(a2, wv.x, accA[j8 * 2 + 0]);
        accA[j8 * 2 + 1] = fma2(a2, wv.y, accA[j8 * 2 + 1]);
        accB[j8 * 2 + 0] = fma2(b2, wv.x, accB[j8 * 2 + 0]);
        accB[j8 * 2 + 1] = fma2(b2, wv.y, accB[j8 * 2 + 1]);
    }
}

// BN(eval)+ReLU for col pair (j, j+1) applied to both nodes' packed values.
__device__ __forceinline__ void bn_pair(ull& va, ull& vb, int j,
    const float* __restrict__ b1, const float* __restrict__ gg,
    const float* __restrict__ bt, const float* __restrict__ rm,
    const float* __restrict__ rv)
{
    float sc0 = __ldg(gg + j)     * rsqrtf(__ldg(rv + j)     + 1e-5f);
    float sc1 = __ldg(gg + j + 1) * rsqrtf(__ldg(rv + j + 1) + 1e-5f);
    float sh0 = (__ldg(b1 + j)     - __ldg(rm + j))     * sc0 + __ldg(bt + j);
    float sh1 = (__ldg(b1 + j + 1) - __ldg(rm + j + 1)) * sc1 + __ldg(bt + j + 1);
    float a, b;
    unpack2(va, a, b);
    a = fmaxf(fmaf(a, sc0, sh0), 0.f);
    b = fmaxf(fmaf(b, sc1, sh1), 0.f);
    va = pack2(a, b);
    unpack2(vb, a, b);
    a = fmaxf(fmaf(a, sc0, sh0), 0.f);
    b = fmaxf(fmaf(b, sc1, sh1), 0.f);
    vb = pack2(a, b);
}

// Epilogue for one node's 32 cols: bias + ReLU + fp16 store + pool reduction.
__device__ __forceinline__ void epi_node(const ull* out16, int halfoff,
                                         const float* __restrict__ b2,
                                         uint2* hrow, float* prow, bool act)
{
    if (!act) return;
    int ubase = halfoff >> 2;
#pragma unroll
    for (int qq = 0; qq < 8; qq++) {
        int j = halfoff + qq * 4;
        float a0, a1, a2, a3;
        unpack2(out16[qq * 2 + 0], a0, a1);
        unpack2(out16[qq * 2 + 1], a2, a3);
        a0 = fmaxf(a0 + __ldg(b2 + j + 0), 0.f);
        a1 = fmaxf(a1 + __ldg(b2 + j + 1), 0.f);
        a2 = fmaxf(a2 + __ldg(b2 + j + 2), 0.f);
        a3 = fmaxf(a3 + __ldg(b2 + j + 3), 0.f);
        hrow[ubase + qq] = f4h(a0, a1, a2, a3);
        asm volatile("red.global.add.v4.f32 [%0], {%1,%2,%3,%4};"
                     :: "l"(prow + j), "f"(a0), "f"(a1), "f"(a2), "f"(a3)
                     : "memory");
    }
}

// ---------------------------------------------------------------------------
__global__ void zero_both_kernel(int* __restrict__ deg, int nd,
                                 float* __restrict__ pool, int np) {
    int i = blockIdx.x * blockDim.x + threadIdx.x;
    if (i < nd) deg[i] = 0;
    if (i < np) pool[i] = 0.f;
}

// ---------------------------------------------------------------------------
// transpose: x [N][128] -> xt [128][N]  (32x32 smem tiles, coalesced)
// ---------------------------------------------------------------------------
__global__ void transpose_kernel(const float* __restrict__ x,
                                 float* __restrict__ xt, int n_nodes) {
    __shared__ float t[32][33];
    int tx = threadIdx.x, ty = threadIdx.y;     // 32 x 8
    int kb = blockIdx.x * 32;
    int nb = blockIdx.y * 32;
#pragma unroll
    for (int r = 0; r < 32; r += 8) {
        int node = nb + ty + r;
        float v = (node < n_nodes) ? __ldg(x + (size_t)node * 128 + kb + tx) : 0.f;
        t[ty + r][tx] = v;
    }
    __syncthreads();
#pragma unroll
    for (int r = 0; r < 32; r += 8) {
        int node = nb + tx;
        if (node < n_nodes)
            xt[(size_t)(kb + ty + r) * n_nodes + node] = t[tx][ty + r];
    }
}

// ---------------------------------------------------------------------------
// CSR build
// ---------------------------------------------------------------------------
__global__ void hist_kernel(const int* __restrict__ ei, int* __restrict__ deg, int n_edges) {
    int e = blockIdx.x * blockDim.x + threadIdx.x;
    if (e < n_edges) atomicAdd(deg + __ldg(ei + n_edges + e), 1);
}

__global__ void bsum_kernel(const int* __restrict__ deg, int* __restrict__ bsum, int n) {
    __shared__ int sm[SCAN_B];
    int i = blockIdx.x * SCAN_B + threadIdx.x;
    sm[threadIdx.x] = (i < n) ? deg[i] : 0;
    __syncthreads();
#pragma unroll
    for (int off = SCAN_B / 2; off > 0; off >>= 1) {
        if (threadIdx.x < off) sm[threadIdx.x] += sm[threadIdx.x + off];
        __syncthreads();
    }
    if (threadIdx.x == 0) bsum[blockIdx.x] = sm[0];
}

// Hillis-Steele block scan; block offset computed INLINE (warp-reduce).
__global__ void scatter_scan_kernel(const int* __restrict__ deg,
                                    const int* __restrict__ bsum,
                                    int* __restrict__ rowptr, int* __restrict__ cur, int n) {
    __shared__ int sm[SCAN_B];
    __shared__ int boff;
    int bid = blockIdx.x;
    if (threadIdx.x < 32) {
        int s = 0;
        for (int i = threadIdx.x; i < bid; i += 32) s += __ldg(bsum + i);
#pragma unroll
        for (int o = 16; o > 0; o >>= 1) s += __shfl_down_sync(0xffffffffu, s, o);
        if (threadIdx.x == 0) boff = s;
    }
    int i = bid * SCAN_B + threadIdx.x;
    int v = (i < n) ? deg[i] : 0;
    sm[threadIdx.x] = v;
    __syncthreads();
#pragma unroll
    for (int off = 1; off < SCAN_B; off *= 2) {
        int t = (threadIdx.x >= off) ? sm[threadIdx.x - off] : 0;
        __syncthreads();
        sm[threadIdx.x] += t;
        __syncthreads();
    }
    int excl = sm[threadIdx.x] - v + boff;
    if (i < n) { rowptr[i] = excl; cur[i] = excl; }
    if (i == n - 1) rowptr[n] = excl + v;
}

__global__ void fill_kernel(const int* __restrict__ ei, int* __restrict__ cur,
                            int* __restrict__ col, int n_edges) {
    int e = blockIdx.x * blockDim.x + threadIdx.x;
    if (e >= n_edges) return;
    int s = __ldg(ei + e);
    int d = __ldg(ei + n_edges + e);
    int pos = atomicAdd(cur + d, 1);
    col[pos] = s;
}

// ---------------------------------------------------------------------------
// Pull aggregation over fp16 rows (fp32 accumulate, fp32 out). 16 thr/node.
// (identical to R9)
// ---------------------------------------------------------------------------
__global__ void pull64h_kernel(const uint2* __restrict__ hh,
                               const int* __restrict__ rowptr,
                               const int* __restrict__ col,
                               float* __restrict__ zout, int n_nodes) {
    int t = blockIdx.x * blockDim.x + threadIdx.x;
    int node = t >> 4, lane = t & 15;
    if (node >= n_nodes) return;
    float4 acc = h2f4(__ldg(hh + (size_t)node * 16 + lane));
    int e   = __ldg(rowptr + node);
    int end = __ldg(rowptr + node + 1);
    for (; e + 8 <= end; e += 8) {
        int s0 = __ldg(col + e),     s1 = __ldg(col + e + 1);
        int s2 = __ldg(col + e + 2), s3 = __ldg(col + e + 3);
        int s4 = __ldg(col + e + 4), s5 = __ldg(col + e + 5);
        int s6 = __ldg(col + e + 6), s7 = __ldg(col + e + 7);
        float4 v0 = h2f4(__ldg(hh + (size_t)s0 * 16 + lane));
        float4 v1 = h2f4(__ldg(hh + (size_t)s1 * 16 + lane));
        float4 v2 = h2f4(__ldg(hh + (size_t)s2 * 16 + lane));
        float4 v3 = h2f4(__ldg(hh + (size_t)s3 * 16 + lane));
        float4 v4 = h2f4(__ldg(hh + (size_t)s4 * 16 + lane));
        float4 v5 = h2f4(__ldg(hh + (size_t)s5 * 16 + lane));
        float4 v6 = h2f4(__ldg(hh + (size_t)s6 * 16 + lane));
        float4 v7 = h2f4(__ldg(hh + (size_t)s7 * 16 + lane));
        acc.x += ((v0.x + v1.x) + (v2.x + v3.x)) + ((v4.x + v5.x) + (v6.x + v7.x));
        acc.y += ((v0.y + v1.y) + (v2.y + v3.y)) + ((v4.y + v5.y) + (v6.y + v7.y));
        acc.z += ((v0.z + v1.z) + (v2.z + v3.z)) + ((v4.z + v5.z) + (v6.z + v7.z));
        acc.w += ((v0.w + v1.w) + (v2.w + v3.w)) + ((v4.w + v5.w) + (v6.w + v7.w));
    }
    for (; e + 4 <= end; e += 4) {
        int s0 = __ldg(col + e),     s1 = __ldg(col + e + 1);
        int s2 = __ldg(col + e + 2), s3 = __ldg(col + e + 3);
        float4 v0 = h2f4(__ldg(hh + (size_t)s0 * 16 + lane));
        float4 v1 = h2f4(__ldg(hh + (size_t)s1 * 16 + lane));
        float4 v2 = h2f4(__ldg(hh + (size_t)s2 * 16 + lane));
        float4 v3 = h2f4(__ldg(hh + (size_t)s3 * 16 + lane));
        acc.x += (v0.x + v1.x) + (v2.x + v3.x);
        acc.y += (v0.y + v1.y) + (v2.y + v3.y);
        acc.z += (v0.z + v1.z) + (v2.z + v3.z);
        acc.w += (v0.w + v1.w) + (v2.w + v3.w);
    }
    for (; e < end; e++) {
        int s = __ldg(col + e);
        float4 v = h2f4(__ldg(hh + (size_t)s * 16 + lane));
        acc.x += v.x; acc.y += v.y; acc.z += v.z; acc.w += v.w;
    }
    ((float4*)zout)[(size_t)node * 16 + lane] = acc;
}

// ---------------------------------------------------------------------------
// gemmA2: hh = fp16(x @ w1) from TRANSPOSED xt.
// Thread = 4 consecutive nodes x 16 cols. Per k: 1 coalesced LDG.128 (xt) +
// 4 broadcast LDS.128 (weights) + 32 FFMA2.
// ---------------------------------------------------------------------------
__global__ __launch_bounds__(128) void gemmA2_kernel(
    const float* __restrict__ xt, const float* __restrict__ w1,
    uint2* __restrict__ hh, int n_nodes)
{
    __shared__ float ws[128 * 64];   // 32KB
    int tid = threadIdx.x;
    for (int i = tid; i < 128 * 64; i += 128) ws[i] = w1[i];
    __syncthreads();

    int qn = tid >> 2, cg = tid & 3;
    int qoff = cg * 16;
    int n0 = blockIdx.x * 128 + 4 * qn;

    // acc[c][jj]: node c (0..3), col pair (qoff+2jj, qoff+2jj+1)
    ull acc[4][8];
#pragma unroll
    for (int c = 0; c < 4; c++)
#pragma unroll
        for (int j = 0; j < 8; j++) acc[c][j] = 0ull;

#pragma unroll 4
    for (int k = 0; k < 128; k++) {
        float4 v = __ldg((const float4*)(xt + (size_t)k * n_nodes + n0));
        const ulonglong2* w = (const ulonglong2*)(ws + k * 64 + qoff);
        ulonglong2 wa = w[0], wb = w[1], wc = w[2], wd = w[3];
        ull w8[8] = {wa.x, wa.y, wb.x, wb.y, wc.x, wc.y, wd.x, wd.y};
        ull p0 = pack2(v.x, v.x), p1 = pack2(v.y, v.y);
        ull p2 = pack2(v.z, v.z), p3 = pack2(v.w, v.w);
#pragma unroll
        for (int jj = 0; jj < 8; jj++) {
            acc[0][jj] = fma2(p0, w8[jj], acc[0][jj]);
            acc[1][jj] = fma2(p1, w8[jj], acc[1][jj]);
            acc[2][jj] = fma2(p2, w8[jj], acc[2][jj]);
            acc[3][jj] = fma2(p3, w8[jj], acc[3][jj]);
        }
    }

    // epilogue: fp16 store of 16 cols per node
#pragma unroll
    for (int c = 0; c < 4; c++) {
        int n = n0 + c;
        if (n >= n_nodes) continue;
        uint2 u[4];
#pragma unroll
        for (int qq = 0; qq < 4; qq++) {
            float a, b, cc, d;
            unpack2(acc[c][qq * 2 + 0], a, b);
            unpack2(acc[c][qq * 2 + 1], cc, d);
            u[qq] = f4h(a, b, cc, d);
        }
        uint4* dst = (uint4*)(hh + (size_t)n * 16 + cg * 4);
        dst[0] = make_uint4(u[0].x, u[0].y, u[1].x, u[1].y);
        dst[1] = make_uint4(u[2].x, u[2].y, u[3].x, u[3].y);
    }
}

// ---------------------------------------------------------------------------
// mlpB (layer-1 tail) — identical to R9
// ---------------------------------------------------------------------------
__global__ __launch_bounds__(128) void mlpB_kernel(
    const float* __restrict__ z,
    const float* __restrict__ b1,
    const float* __restrict__ gg, const float* __restrict__ bt,
    const float* __restrict__ rm, const float* __restrict__ rv,
    const float* __restrict__ w2, const float* __restrict__ b2,
    uint2*       __restrict__ hh,
    const int*   __restrict__ batch,
    float*       __restrict__ pool, int pool_off, int n_nodes)
{
    __shared__ float ws[64 * 64];      // 16KB (w2)
    __shared__ float tile[64 * 128];   // 32KB [col][node]
    int tid = threadIdx.x;
    for (int i = tid; i < 64 * 64; i += 128) ws[i] = w2[i];

    int half = tid & 1, q = tid >> 1;
    int halfoff = half * 32;
    int n0 = blockIdx.x * 128 + 2 * q, n1 = n0 + 1;
    bool a0 = n0 < n_nodes, a1 = n1 < n_nodes;
    int n0c = a0 ? n0 : n_nodes - 1, n1c = a1 ? n1 : n_nodes - 1;

    const float4* zr0 = (const float4*)(z + (size_t)n0c * 64 + halfoff);
    const float4* zr1 = (const float4*)(z + (size_t)n1c * 64 + halfoff);
#pragma unroll
    for (int qq = 0; qq < 8; qq++) {
        float4 v0 = __ldg(zr0 + qq), v1 = __ldg(zr1 + qq);
        ull p00 = pack2(v0.x, v0.y), p01 = pack2(v0.z, v0.w);
        ull p10 = pack2(v1.x, v1.y), p11 = pack2(v1.z, v1.w);
        int j = halfoff + qq * 4;
        bn_pair(p00, p10, j,     b1, gg, bt, rm, rv);
        bn_pair(p01, p11, j + 2, b1, gg, bt, rm, rv);
        float x0, x1, y0, y1;
        unpack2(p00, x0, x1); unpack2(p10, y0, y1);
        *(float2*)&tile[(j + 0) * 128 + 2 * q] = make_float2(x0, y0);
        *(float2*)&tile[(j + 1) * 128 + 2 * q] = make_float2(x1, y1);
        unpack2(p01, x0, x1); unpack2(p11, y0, y1);
        *(float2*)&tile[(j + 2) * 128 + 2 * q] = make_float2(x0, y0);
        *(float2*)&tile[(j + 3) * 128 + 2 * q] = make_float2(x1, y1);
    }
    __syncthreads();

    ull out[2][16];
#pragma unroll
    for (int j = 0; j < 16; j++) { out[0][j] = 0ull; out[1][j] = 0ull; }
#pragma unroll 4
    for (int k = 0; k < 64; k++) {
        float2 hv = *(const float2*)&tile[k * 128 + 2 * q];
        fma_k32_dual(out[0], out[1], ws, k, halfoff, hv.x, hv.y);
    }

    uint2* o0 = hh + (size_t)n0 * 16;
    uint2* o1 = hh + (size_t)n1 * 16;
    float* p0 = a0 ? (pool + (size_t)__ldg(batch + n0) * 192 + pool_off) : pool;
    float* p1 = a1 ? (pool + (size_t)__ldg(batch + n1) * 192 + pool_off) : pool;
    epi_node(out[0], halfoff, b2, o0, p0, a0);
    epi_node(out[1], halfoff, b2, o1, p1, a1);
}

// ---------------------------------------------------------------------------
// mlp64 (layers 2/3) — identical to R9
// ---------------------------------------------------------------------------
__global__ __launch_bounds__(128) void mlp64_kernel(
    const float* __restrict__ agg,
    const float* __restrict__ w1, const float* __restrict__ b1,
    const float* __restrict__ gg, const float* __restrict__ bt,
    const float* __restrict__ rm, const float* __restrict__ rv,
    const float* __restrict__ w2, const float* __restrict__ b2,
    uint2*       __restrict__ hh,
    const int*   __restrict__ batch,
    float*       __restrict__ pool, int pool_off, int n_nodes)
{
    __shared__ float ws[64 * 64];      // 16KB (w1 then w2)
    __shared__ float tile[64 * 128];   // 32KB [col][node]
    int tid = threadIdx.x;
    for (int i = tid; i < 64 * 64; i += 128) ws[i] = w1[i];
    __syncthreads();

    int half = tid & 1, q = tid >> 1;
    int halfoff = half * 32;
    int n0 = blockIdx.x * 128 + 2 * q, n1 = n0 + 1;
    bool a0 = n0 < n_nodes, a1 = n1 < n_nodes;
    int n0c = a0 ? n0 : n_nodes - 1, n1c = a1 ? n1 : n_nodes - 1;

    ull acc[2][16];
#pragma unroll
    for (int j = 0; j < 16; j++) { acc[0][j] = 0ull; acc[1][j] = 0ull; }

    const float4* r0 = (const float4*)(agg + (size_t)n0c * 64);
    const float4* r1 = (const float4*)(agg + (size_t)n1c * 64);
#pragma unroll 4
    for (int k4 = 0; k4 < 16; k4++) {
        float4 v0 = __ldg(r0 + k4), v1 = __ldg(r1 + k4);
        float f0[4] = {v0.x, v0.y, v0.z, v0.w};
        float f1[4] = {v1.x, v1.y, v1.z, v1.w};
#pragma unroll
        for (int kk = 0; kk < 4; kk++)
            fma_k32_dual(acc[0], acc[1], ws, k4 * 4 + kk, halfoff, f0[kk], f1[kk]);
    }

#pragma unroll
    for (int j2 = 0; j2 < 16; j2++) {
        int j = halfoff + 2 * j2;
        bn_pair(acc[0][j2], acc[1][j2], j, b1, gg, bt, rm, rv);
        float x0, x1, y0, y1;
        unpack2(acc[0][j2], x0, x1);
        unpack2(acc[1][j2], y0, y1);
        *(float2*)&tile[(j + 0) * 128 + 2 * q] = make_float2(x0, y0);
        *(float2*)&tile[(j + 1) * 128 + 2 * q] = make_float2(x1, y1);
    }

    __syncthreads();
    for (int i = tid; i < 64 * 64; i += 128) ws[i] = w2[i];
    __syncthreads();

    ull out[2][16];
#pragma unroll
    for (int j = 0; j < 16; j++) { out[0][j] = 0ull; out[1][j] = 0ull; }
#pragma unroll 4
    for (int k = 0; k < 64; k++) {
        float2 hv = *(const float2*)&tile[k * 128 + 2 * q];
        fma_k32_dual(out[0], out[1], ws, k, halfoff, hv.x, hv.y);
    }

    uint2* o0 = hh + (size_t)n0 * 16;
    uint2* o1 = hh + (size_t)n1 * 16;
    float* p0 = a0 ? (pool + (size_t)__ldg(batch + n0) * 192 + pool_off) : pool;
    float* p1 = a1 ? (pool + (size_t)__ldg(batch + n1) * 192 + pool_off) : pool;
    epi_node(out[0], halfoff, b2, o0, p0, a0);
    epi_node(out[1], halfoff, b2, o1, p1, a1);
}

// ---------------------------------------------------------------------------
__global__ void final_kernel(const float* __restrict__ pool,
                             const float* __restrict__ lw1, const float* __restrict__ lb1,
                             const float* __restrict__ lw2, const float* __restrict__ lb2,
                             float* __restrict__ out)
{
    __shared__ float prow[192];
    __shared__ float hid[64];
    __shared__ float zz[2];
    int g = blockIdx.x, j = threadIdx.x;
    for (int k = j; k < 192; k += 64) prow[k] = pool[g * 192 + k];
    __syncthreads();
    float a = __ldg(lb1 + j);
    for (int k = 0; k < 192; k++) a = fmaf(prow[k], __ldg(lw1 + k * 64 + j), a);
    hid[j] = fmaxf(a, 0.f);
    __syncthreads();
    if (j < 2) {
        float z = __ldg(lb2 + j);
#pragma unroll 8
        for (int k = 0; k < 64; k++) z = fmaf(hid[k], __ldg(lw2 + k * 2 + j), z);
        zz[j] = z;
    }
    __syncthreads();
    if (j == 0) {
        float m   = fmaxf(zz[0], zz[1]);
        float lse = m + logf(expf(zz[0] - m) + expf(zz[1] - m));
        out[g * 2 + 0] = zz[0] - lse;
        out[g * 2 + 1] = zz[1] - lse;
    }
}

// ---------------------------------------------------------------------------
extern "C" void kernel_launch(void* const* d_in, const int* in_sizes, int n_in,
                              void* d_out, int out_size)
{
    const float* x     = (const float*)d_in[0];
    const int*   ei    = (const int*)  d_in[1];
    const int*   batch = (const int*)  d_in[2];

    int wi = (in_sizes[3] < 64) ? 4 : 3;
    const float* W[28];
    for (int i = 0; i < 28 && wi + i < n_in; i++) W[i] = (const float*)d_in[wi + i];

    int n_nodes = in_sizes[0] / 128;
    int n_edges = in_sizes[1] / 2;

    float *z, *xt, *pool;
    uint2 *hh;
    int *deg, *row, *cur, *col, *bsum;
    cudaGetSymbolAddress((void**)&z,    g_z);
    cudaGetSymbolAddress((void**)&xt,   g_xt);
    cudaGetSymbolAddress((void**)&hh,   g_hh);
    cudaGetSymbolAddress((void**)&pool, g_pool);
    cudaGetSymbolAddress((void**)&deg,  g_deg);
    cudaGetSymbolAddress((void**)&row,  g_row);
    cudaGetSymbolAddress((void**)&cur,  g_cur);
    cudaGetSymbolAddress((void**)&col,  g_col);
    cudaGetSymbolAddress((void**)&bsum, g_bsum);

    float* out = (float*)d_out;

    int mlpBlocks  = (n_nodes + 127) / 128;
    int pullBlocks = (n_nodes * 16 + 255) / 256;
    int scanBlocks = (n_nodes + SCAN_B - 1) / SCAN_B;
    int zeroN      = n_nodes + 1;

    dim3 tBlk(32, 8), tGrid(4, (n_nodes + 31) / 32);

    // ---- CSR build + transpose; gemmA2 is OUR launch #4 (profiled) ----
    zero_both_kernel<<<(zeroN + 255) / 256, 256>>>(deg, zeroN, pool, NGRAPH * 192); // 1
    hist_kernel<<<(n_edges + 255) / 256, 256>>>(ei, deg, n_edges);                  // 2
    transpose_kernel<<<tGrid, tBlk>>>(x, xt, n_nodes);                              // 3
    gemmA2_kernel<<<mlpBlocks, 128>>>(xt, W[0], hh, n_nodes);                       // 4
    bsum_kernel<<<scanBlocks, SCAN_B>>>(deg, bsum, n_nodes);                        // 5
    scatter_scan_kernel<<<scanBlocks, SCAN_B>>>(deg, bsum, row, cur, n_nodes);      // 6
    fill_kernel<<<(n_edges + 255) / 256, 256>>>(ei, cur, col, n_edges);             // 7

    // ---- layer 1 ----
    pull64h_kernel<<<pullBlocks, 256>>>(hh, row, col, z, n_nodes);                  // 8
    mlpB_kernel<<<mlpBlocks, 128>>>(z, W[1], W[2], W[3], W[4], W[5], W[6], W[7],
                                    hh, batch, pool, 0, n_nodes);                   // 9

    // ---- layer 2 ----
    pull64h_kernel<<<pullBlocks, 256>>>(hh, row, col, z, n_nodes);                  // 10
    mlp64_kernel<<<mlpBlocks, 128>>>(z, W[8], W[9], W[10], W[11], W[12], W[13], W[14], W[15],
                                     hh, batch, pool, 64, n_nodes);                 // 11

    // ---- layer 3 ----
    pull64h_kernel<<<pullBlocks, 256>>>(hh, row, col, z, n_nodes);                  // 12
    mlp64_kernel<<<mlpBlocks, 128>>>(z, W[16], W[17], W[18], W[19], W[20], W[21], W[22], W[23],
                                     hh, batch, pool, 128, n_nodes);                // 13

    final_kernel<<<NGRAPH, 64>>>(pool, W[24], W[25], W[26], W[27], out);            // 14
}

// round 13
// speedup vs baseline: 1.1900x; 1.1900x over previous
#include <cuda_runtime.h>
#include <cuda_fp16.h>
#include <math.h>

// ---------------------------------------------------------------------------
// GIN (3 GINConv layers + BN + ReLU + MLP head)
//   N_NODES=100000, N_EDGES=1200000, D_IN=128, D_H=64, N_GRAPHS=256
// R12 = R11 resubmitted (infra failure, kernel never ran):
//   * gemmA on TENSOR CORES: mma.sync.m16n8k16 f16f16f32.
//     x loaded coalesced -> fp16 smem A tile; w1 -> fp16 Bs[n][k] (col-major B).
//     Manual canonical fragment loads (conflict-free, no ldmatrix).
//   * mlpB / mlp64 / pull / CSR / final byte-identical to R9 (454.7us base).
// ---------------------------------------------------------------------------

#define MAX_NODES 100000
#define MAX_EDGES 1200000
#define NGRAPH    256
#define SCAN_B    1024
#define MAX_SCAN_BLOCKS 128
#define APAD 136                    // halves stride of A tile rows (128+8)
#define BPAD 136                    // halves stride of Bs rows

__device__ float g_z   [MAX_NODES * 64];          // fp32 aggregated rows
__device__ uint2 g_hh  [MAX_NODES * 16 + 16];     // fp16 activation rows + pad
__device__ float g_pool[NGRAPH * 192];
__device__ int   g_deg [MAX_NODES + 1];
__device__ int   g_row [MAX_NODES + 1];
__device__ int   g_cur [MAX_NODES];
__device__ int   g_col [MAX_EDGES];
__device__ int   g_bsum[MAX_SCAN_BLOCKS];

typedef unsigned long long ull;

__device__ __forceinline__ ull pack2(float lo, float hi) {
    ull r; asm("mov.b64 %0,{%1,%2};" : "=l"(r) : "f"(lo), "f"(hi)); return r;
}
__device__ __forceinline__ void unpack2(ull v, float& lo, float& hi) {
    asm("mov.b64 {%0,%1},%2;" : "=f"(lo), "=f"(hi) : "l"(v));
}
__device__ __forceinline__ ull fma2(ull a, ull b, ull c) {
    ull d; asm("fma.rn.f32x2 %0,%1,%2,%3;" : "=l"(d) : "l"(a), "l"(b), "l"(c)); return d;
}
__device__ __forceinline__ float4 h2f4(uint2 u) {
    __half2 a = *(__half2*)&u.x, b = *(__half2*)&u.y;
    float2 fa = __half22float2(a), fb = __half22float2(b);
    return make_float4(fa.x, fa.y, fb.x, fb.y);
}
__device__ __forceinline__ uint2 f4h(float a, float b, float c, float d) {
    __half2 lo = __floats2half2_rn(a, b), hi = __floats2half2_rn(c, d);
    uint2 u; u.x = *(unsigned*)&lo; u.y = *(unsigned*)&hi; return u;
}

__device__ __forceinline__ void mma16816(float* c,
    unsigned a0, unsigned a1, unsigned a2, unsigned a3,
    unsigned b0, unsigned b1)
{
    asm volatile(
        "mma.sync.aligned.m16n8k16.row.col.f32.f16.f16.f32 "
        "{%0,%1,%2,%3}, {%4,%5,%6,%7}, {%8,%9}, {%0,%1,%2,%3};"
        : "+f"(c[0]), "+f"(c[1]), "+f"(c[2]), "+f"(c[3])
        : "r"(a0), "r"(a1), "r"(a2), "r"(a3), "r"(b0), "r"(b1));
}

// One k-step: one weight row segment (32 cols) feeds TWO nodes' accumulators.
__device__ __forceinline__ void fma_k32_dual(ull* accA, ull* accB,
                                             const float* ws, int k, int halfoff,
                                             float va, float vb) {
    ull a2 = pack2(va, va), b2 = pack2(vb, vb);
    const ulonglong2* wrow = (const ulonglong2*)(ws + k * 64 + halfoff);
#pragma unroll
    for (int j8 = 0; j8 < 8; j8++) {
        ulonglong2 wv = wrow[j8];
        accA[j8 * 2 + 0] = fma2(a2, wv.x, accA[j8 * 2 + 0]);
        accA[j8 * 2 + 1] = fma2(a2, wv.y, accA[j8 * 2 + 1]);
        accB[j8 * 2 + 0] = fma2(b2, wv.x, accB[j8 * 2 + 0]);
        accB[j8 * 2 + 1] = fma2(b2, wv.y, accB[j8 * 2 + 1]);
    }
}

// BN(eval)+ReLU for col pair (j, j+1) applied to both nodes' packed values.
__device__ __forceinline__ void bn_pair(ull& va, ull& vb, int j,
    const float* __restrict__ b1, const float* __restrict__ gg,
    const float* __restrict__ bt, const float* __restrict__ rm,
    const float* __restrict__ rv)
{
    float sc0 = __ldg(gg + j)     * rsqrtf(__ldg(rv + j)     + 1e-5f);
    float sc1 = __ldg(gg + j + 1) * rsqrtf(__ldg(rv + j + 1) + 1e-5f);
    float sh0 = (__ldg(b1 + j)     - __ldg(rm + j))     * sc0 + __ldg(bt + j);
    float sh1 = (__ldg(b1 + j + 1) - __ldg(rm + j + 1)) * sc1 + __ldg(bt + j + 1);
    float a, b;
    unpack2(va, a, b);
    a = fmaxf(fmaf(a, sc0, sh0), 0.f);
    b = fmaxf(fmaf(b, sc1, sh1), 0.f);
    va = pack2(a, b);
    unpack2(vb, a, b);
    a = fmaxf(fmaf(a, sc0, sh0), 0.f);
    b = fmaxf(fmaf(b, sc1, sh1), 0.f);
    vb = pack2(a, b);
}

// Epilogue for one node's 32 cols: bias + ReLU + fp16 store + pool reduction.
__device__ __forceinline__ void epi_node(const ull* out16, int halfoff,
                                         const float* __restrict__ b2,
                                         uint2* hrow, float* prow, bool act)
{
    if (!act) return;
    int ubase = halfoff >> 2;
#pragma unroll
    for (int qq = 0; qq < 8; qq++) {
        int j = halfoff + qq * 4;
        float a0, a1, a2, a3;
        unpack2(out16[qq * 2 + 0], a0, a1);
        unpack2(out16[qq * 2 + 1], a2, a3);
        a0 = fmaxf(a0 + __ldg(b2 + j + 0), 0.f);
        a1 = fmaxf(a1 + __ldg(b2 + j + 1), 0.f);
        a2 = fmaxf(a2 + __ldg(b2 + j + 2), 0.f);
        a3 = fmaxf(a3 + __ldg(b2 + j + 3), 0.f);
        hrow[ubase + qq] = f4h(a0, a1, a2, a3);
        asm volatile("red.global.add.v4.f32 [%0], {%1,%2,%3,%4};"
                     :: "l"(prow + j), "f"(a0), "f"(a1), "f"(a2), "f"(a3)
                     : "memory");
    }
}

// ---------------------------------------------------------------------------
__global__ void zero_both_kernel(int* __restrict__ deg, int nd,
                                 float* __restrict__ pool, int np) {
    int i = blockIdx.x * blockDim.x + threadIdx.x;
    if (i < nd) deg[i] = 0;
    if (i < np) pool[i] = 0.f;
}

// ---------------------------------------------------------------------------
// CSR build
// ---------------------------------------------------------------------------
__global__ void hist_kernel(const int* __restrict__ ei, int* __restrict__ deg, int n_edges) {
    int e = blockIdx.x * blockDim.x + threadIdx.x;
    if (e < n_edges) atomicAdd(deg + __ldg(ei + n_edges + e), 1);
}

__global__ void bsum_kernel(const int* __restrict__ deg, int* __restrict__ bsum, int n) {
    __shared__ int sm[SCAN_B];
    int i = blockIdx.x * SCAN_B + threadIdx.x;
    sm[threadIdx.x] = (i < n) ? deg[i] : 0;
    __syncthreads();
#pragma unroll
    for (int off = SCAN_B / 2; off > 0; off >>= 1) {
        if (threadIdx.x < off) sm[threadIdx.x] += sm[threadIdx.x + off];
        __syncthreads();
    }
    if (threadIdx.x == 0) bsum[blockIdx.x] = sm[0];
}

__global__ void scatter_scan_kernel(const int* __restrict__ deg,
                                    const int* __restrict__ bsum,
                                    int* __restrict__ rowptr, int* __restrict__ cur, int n) {
    __shared__ int sm[SCAN_B];
    __shared__ int boff;
    int bid = blockIdx.x;
    if (threadIdx.x < 32) {
        int s = 0;
        for (int i = threadIdx.x; i < bid; i += 32) s += __ldg(bsum + i);
#pragma unroll
        for (int o = 16; o > 0; o >>= 1) s += __shfl_down_sync(0xffffffffu, s, o);
        if (threadIdx.x == 0) boff = s;
    }
    int i = bid * SCAN_B + threadIdx.x;
    int v = (i < n) ? deg[i] : 0;
    sm[threadIdx.x] = v;
    __syncthreads();
#pragma unroll
    for (int off = 1; off < SCAN_B; off *= 2) {
        int t = (threadIdx.x >= off) ? sm[threadIdx.x - off] : 0;
        __syncthreads();
        sm[threadIdx.x] += t;
        __syncthreads();
    }
    int excl = sm[threadIdx.x] - v + boff;
    if (i < n) { rowptr[i] = excl; cur[i] = excl; }
    if (i == n - 1) rowptr[n] = excl + v;
}

__global__ void fill_kernel(const int* __restrict__ ei, int* __restrict__ cur,
                            int* __restrict__ col, int n_edges) {
    int e = blockIdx.x * blockDim.x + threadIdx.x;
    if (e >= n_edges) return;
    int s = __ldg(ei + e);
    int d = __ldg(ei + n_edges + e);
    int pos = atomicAdd(cur + d, 1);
    col[pos] = s;
}

// ---------------------------------------------------------------------------
// Pull aggregation over fp16 rows (fp32 accumulate, fp32 out). 16 thr/node.
// ---------------------------------------------------------------------------
__global__ void pull64h_kernel(const uint2* __restrict__ hh,
                               const int* __restrict__ rowptr,
                               const int* __restrict__ col,
                               float* __restrict__ zout, int n_nodes) {
    int t = blockIdx.x * blockDim.x + threadIdx.x;
    int node = t >> 4, lane = t & 15;
    if (node >= n_nodes) return;
    float4 acc = h2f4(__ldg(hh + (size_t)node * 16 + lane));
    int e   = __ldg(rowptr + node);
    int end = __ldg(rowptr + node + 1);
    for (; e + 8 <= end; e += 8) {
        int s0 = __ldg(col + e),     s1 = __ldg(col + e + 1);
        int s2 = __ldg(col + e + 2), s3 = __ldg(col + e + 3);
        int s4 = __ldg(col + e + 4), s5 = __ldg(col + e + 5);
        int s6 = __ldg(col + e + 6), s7 = __ldg(col + e + 7);
        float4 v0 = h2f4(__ldg(hh + (size_t)s0 * 16 + lane));
        float4 v1 = h2f4(__ldg(hh + (size_t)s1 * 16 + lane));
        float4 v2 = h2f4(__ldg(hh + (size_t)s2 * 16 + lane));
        float4 v3 = h2f4(__ldg(hh + (size_t)s3 * 16 + lane));
        float4 v4 = h2f4(__ldg(hh + (size_t)s4 * 16 + lane));
        float4 v5 = h2f4(__ldg(hh + (size_t)s5 * 16 + lane));
        float4 v6 = h2f4(__ldg(hh + (size_t)s6 * 16 + lane));
        float4 v7 = h2f4(__ldg(hh + (size_t)s7 * 16 + lane));
        acc.x += ((v0.x + v1.x) + (v2.x + v3.x)) + ((v4.x + v5.x) + (v6.x + v7.x));
        acc.y += ((v0.y + v1.y) + (v2.y + v3.y)) + ((v4.y + v5.y) + (v6.y + v7.y));
        acc.z += ((v0.z + v1.z) + (v2.z + v3.z)) + ((v4.z + v5.z) + (v6.z + v7.z));
        acc.w += ((v0.w + v1.w) + (v2.w + v3.w)) + ((v4.w + v5.w) + (v6.w + v7.w));
    }
    for (; e + 4 <= end; e += 4) {
        int s0 = __ldg(col + e),     s1 = __ldg(col + e + 1);
        int s2 = __ldg(col + e + 2), s3 = __ldg(col + e + 3);
        float4 v0 = h2f4(__ldg(hh + (size_t)s0 * 16 + lane));
        float4 v1 = h2f4(__ldg(hh + (size_t)s1 * 16 + lane));
        float4 v2 = h2f4(__ldg(hh + (size_t)s2 * 16 + lane));
        float4 v3 = h2f4(__ldg(hh + (size_t)s3 * 16 + lane));
        acc.x += (v0.x + v1.x) + (v2.x + v3.x);
        acc.y += (v0.y + v1.y) + (v2.y + v3.y);
        acc.z += (v0.z + v1.z) + (v2.z + v3.z);
        acc.w += (v0.w + v1.w) + (v2.w + v3.w);
    }
    for (; e < end; e++) {
        int s = __ldg(col + e);
        float4 v = h2f4(__ldg(hh + (size_t)s * 16 + lane));
        acc.x += v.x; acc.y += v.y; acc.z += v.z; acc.w += v.w;
    }
    ((float4*)zout)[(size_t)node * 16 + lane] = acc;
}

// ---------------------------------------------------------------------------
// gemmA_hmma: hh = fp16(x @ w1) on tensor cores (m16n8k16 f16f16f32).
// Block: 256 threads (8 warps), 128 nodes. Warp w -> rows [w*16, w*16+16).
// A tile As[128][APAD] fp16 (x rows, coalesced load); Bs[n][k] fp16 (w1^T).
// ---------------------------------------------------------------------------
__global__ __launch_bounds__(256) void gemmA_hmma_kernel(
    const float* __restrict__ x, const float* __restrict__ w1,
    uint2* __restrict__ hh, int n_nodes)
{
    extern __shared__ __half dsm[];
    __half* As = dsm;                  // [128][APAD]
    __half* Bs = dsm + 128 * APAD;     // [64][BPAD]
    int tid = threadIdx.x;
    int nbase = blockIdx.x * 128;

    // ---- load x tile (coalesced float4, rows contiguous per block) ----
    for (int i4 = tid; i4 < 4096; i4 += 256) {
        int row = i4 >> 5, k4 = i4 & 31;
        int gn = nbase + row; if (gn >= n_nodes) gn = n_nodes - 1;
        float4 v = __ldg((const float4*)(x + (size_t)gn * 128) + k4);
        __half2 h0 = __floats2half2_rn(v.x, v.y);
        __half2 h1 = __floats2half2_rn(v.z, v.w);
        unsigned* dst = (unsigned*)&As[row * APAD + k4 * 4];
        dst[0] = *(unsigned*)&h0;
        dst[1] = *(unsigned*)&h1;
    }
    // ---- load w1 -> Bs[n][k] (transposed, k contiguous) ----
    for (int i = tid; i < 128 * 64; i += 256) {
        int k = i >> 6, n = i & 63;
        Bs[n * BPAD + k] = __float2half(__ldg(w1 + i));
    }
    __syncthreads();

    int wid = tid >> 5, lane = tid & 31;
    int mbase = wid * 16;
    int r0 = mbase + (lane >> 2);
    int kp = (lane & 3) * 2;

    float c[8][4];
#pragma unroll
    for (int nt = 0; nt < 8; nt++)
#pragma unroll
        for (int j = 0; j < 4; j++) c[nt][j] = 0.f;

#pragma unroll
    for (int kt = 0; kt < 8; kt++) {
        int kb = kt * 16 + kp;
        unsigned a0 = *(unsigned*)&As[r0 * APAD + kb];
        unsigned a1 = *(unsigned*)&As[(r0 + 8) * APAD + kb];
        unsigned a2 = *(unsigned*)&As[r0 * APAD + kb + 8];
        unsigned a3 = *(unsigned*)&As[(r0 + 8) * APAD + kb + 8];
#pragma unroll
        for (int nt = 0; nt < 8; nt++) {
            int n = nt * 8 + (lane >> 2);
            unsigned b0 = *(unsigned*)&Bs[n * BPAD + kb];
            unsigned b1 = *(unsigned*)&Bs[n * BPAD + kb + 8];
            mma16816(c[nt], a0, a1, a2, a3, b0, b1);
        }
    }

    // ---- epilogue: fp16 stores (row, col),(row,col+1) per fragment ----
    int colp = (lane & 3) * 2;
#pragma unroll
    for (int rr = 0; rr < 2; rr++) {
        int node = nbase + r0 + rr * 8;
        if (node >= n_nodes) continue;
        __half* hrow = (__half*)(hh + (size_t)node * 16);
#pragma unroll
        for (int nt = 0; nt < 8; nt++) {
            __half2 hv = __floats2half2_rn(c[nt][rr * 2 + 0], c[nt][rr * 2 + 1]);
            *(unsigned*)&hrow[nt * 8 + colp] = *(unsigned*)&hv;
        }
    }
}

// ---------------------------------------------------------------------------
// mlpB (layer-1 tail) — identical to R9
// ---------------------------------------------------------------------------
__global__ __launch_bounds__(128) void mlpB_kernel(
    const float* __restrict__ z,
    const float* __restrict__ b1,
    const float* __restrict__ gg, const float* __restrict__ bt,
    const float* __restrict__ rm, const float* __restrict__ rv,
    const float* __restrict__ w2, const float* __restrict__ b2,
    uint2*       __restrict__ hh,
    const int*   __restrict__ batch,
    float*       __restrict__ pool, int pool_off, int n_nodes)
{
    __shared__ float ws[64 * 64];      // 16KB (w2)
    __shared__ float tile[64 * 128];   // 32KB [col][node]
    int tid = threadIdx.x;
    for (int i = tid; i < 64 * 64; i += 128) ws[i] = w2[i];

    int half = tid & 1, q = tid >> 1;
    int halfoff = half * 32;
    int n0 = blockIdx.x * 128 + 2 * q, n1 = n0 + 1;
    bool a0 = n0 < n_nodes, a1 = n1 < n_nodes;
    int n0c = a0 ? n0 : n_nodes - 1, n1c = a1 ? n1 : n_nodes - 1;

    const float4* zr0 = (const float4*)(z + (size_t)n0c * 64 + halfoff);
    const float4* zr1 = (const float4*)(z + (size_t)n1c * 64 + halfoff);
#pragma unroll
    for (int qq = 0; qq < 8; qq++) {
        float4 v0 = __ldg(zr0 + qq), v1 = __ldg(zr1 + qq);
        ull p00 = pack2(v0.x, v0.y), p01 = pack2(v0.z, v0.w);
        ull p10 = pack2(v1.x, v1.y), p11 = pack2(v1.z, v1.w);
        int j = halfoff + qq * 4;
        bn_pair(p00, p10, j,     b1, gg, bt, rm, rv);
        bn_pair(p01, p11, j + 2, b1, gg, bt, rm, rv);
        float x0, x1, y0, y1;
        unpack2(p00, x0, x1); unpack2(p10, y0, y1);
        *(float2*)&tile[(j + 0) * 128 + 2 * q] = make_float2(x0, y0);
        *(float2*)&tile[(j + 1) * 128 + 2 * q] = make_float2(x1, y1);
        unpack2(p01, x0, x1); unpack2(p11, y0, y1);
        *(float2*)&tile[(j + 2) * 128 + 2 * q] = make_float2(x0, y0);
        *(float2*)&tile[(j + 3) * 128 + 2 * q] = make_float2(x1, y1);
    }
    __syncthreads();

    ull out[2][16];
#pragma unroll
    for (int j = 0; j < 16; j++) { out[0][j] = 0ull; out[1][j] = 0ull; }
#pragma unroll 4
    for (int k = 0; k < 64; k++) {
        float2 hv = *(const float2*)&tile[k * 128 + 2 * q];
        fma_k32_dual(out[0], out[1], ws, k, halfoff, hv.x, hv.y);
    }

    uint2* o0 = hh + (size_t)n0 * 16;
    uint2* o1 = hh + (size_t)n1 * 16;
    float* p0 = a0 ? (pool + (size_t)__ldg(batch + n0) * 192 + pool_off) : pool;
    float* p1 = a1 ? (pool + (size_t)__ldg(batch + n1) * 192 + pool_off) : pool;
    epi_node(out[0], halfoff, b2, o0, p0, a0);
    epi_node(out[1], halfoff, b2, o1, p1, a1);
}

// ---------------------------------------------------------------------------
// mlp64 (layers 2/3) — identical to R9
// ---------------------------------------------------------------------------
__global__ __launch_bounds__(128) void mlp64_kernel(
    const float* __restrict__ agg,
    const float* __restrict__ w1, const float* __restrict__ b1,
    const float* __restrict__ gg, const float* __restrict__ bt,
    const float* __restrict__ rm, const float* __restrict__ rv,
    const float* __restrict__ w2, const float* __restrict__ b2,
    uint2*       __restrict__ hh,
    const int*   __restrict__ batch,
    float*       __restrict__ pool, int pool_off, int n_nodes)
{
    __shared__ float ws[64 * 64];      // 16KB (w1 then w2)
    __shared__ float tile[64 * 128];   // 32KB [col][node]
    int tid = threadIdx.x;
    for (int i = tid; i < 64 * 64; i += 128) ws[i] = w1[i];
    __syncthreads();

    int half = tid & 1, q = tid >> 1;
    int halfoff = half * 32;
    int n0 = blockIdx.x * 128 + 2 * q, n1 = n0 + 1;
    bool a0 = n0 < n_nodes, a1 = n1 < n_nodes;
    int n0c = a0 ? n0 : n_nodes - 1, n1c = a1 ? n1 : n_nodes - 1;

    ull acc[2][16];
#pragma unroll
    for (int j = 0; j < 16; j++) { acc[0][j] = 0ull; acc[1][j] = 0ull; }

    const float4* r0 = (const float4*)(agg + (size_t)n0c * 64);
    const float4* r1 = (const float4*)(agg + (size_t)n1c * 64);
#pragma unroll 4
    for (int k4 = 0; k4 < 16; k4++) {
        float4 v0 = __ldg(r0 + k4), v1 = __ldg(r1 + k4);
        float f0[4] = {v0.x, v0.y, v0.z, v0.w};
        float f1[4] = {v1.x, v1.y, v1.z, v1.w};
#pragma unroll
        for (int kk = 0; kk < 4; kk++)
            fma_k32_dual(acc[0], acc[1], ws, k4 * 4 + kk, halfoff, f0[kk], f1[kk]);
    }

#pragma unroll
    for (int j2 = 0; j2 < 16; j2++) {
        int j = halfoff + 2 * j2;
        bn_pair(acc[0][j2], acc[1][j2], j, b1, gg, bt, rm, rv);
        float x0, x1, y0, y1;
        unpack2(acc[0][j2], x0, x1);
        unpack2(acc[1][j2], y0, y1);
        *(float2*)&tile[(j + 0) * 128 + 2 * q] = make_float2(x0, y0);
        *(float2*)&tile[(j + 1) * 128 + 2 * q] = make_float2(x1, y1);
    }

    __syncthreads();
    for (int i = tid; i < 64 * 64; i += 128) ws[i] = w2[i];
    __syncthreads();

    ull out[2][16];
#pragma unroll
    for (int j = 0; j < 16; j++) { out[0][j] = 0ull; out[1][j] = 0ull; }
#pragma unroll 4
    for (int k = 0; k < 64; k++) {
        float2 hv = *(const float2*)&tile[k * 128 + 2 * q];
        fma_k32_dual(out[0], out[1], ws, k, halfoff, hv.x, hv.y);
    }

    uint2* o0 = hh + (size_t)n0 * 16;
    uint2* o1 = hh + (size_t)n1 * 16;
    float* p0 = a0 ? (pool + (size_t)__ldg(batch + n0) * 192 + pool_off) : pool;
    float* p1 = a1 ? (pool + (size_t)__ldg(batch + n1) * 192 + pool_off) : pool;
    epi_node(out[0], halfoff, b2, o0, p0, a0);
    epi_node(out[1], halfoff, b2, o1, p1, a1);
}

// ---------------------------------------------------------------------------
__global__ void final_kernel(const float* __restrict__ pool,
                             const float* __restrict__ lw1, const float* __restrict__ lb1,
                             const float* __restrict__ lw2, const float* __restrict__ lb2,
                             float* __restrict__ out)
{
    __shared__ float prow[192];
    __shared__ float hid[64];
    __shared__ float zz[2];
    int g = blockIdx.x, j = threadIdx.x;
    for (int k = j; k < 192; k += 64) prow[k] = pool[g * 192 + k];
    __syncthreads();
    float a = __ldg(lb1 + j);
    for (int k = 0; k < 192; k++) a = fmaf(prow[k], __ldg(lw1 + k * 64 + j), a);
    hid[j] = fmaxf(a, 0.f);
    __syncthreads();
    if (j < 2) {
        float z = __ldg(lb2 + j);
#pragma unroll 8
        for (int k = 0; k < 64; k++) z = fmaf(hid[k], __ldg(lw2 + k * 2 + j), z);
        zz[j] = z;
    }
    __syncthreads();
    if (j == 0) {
        float m   = fmaxf(zz[0], zz[1]);
        float lse = m + logf(expf(zz[0] - m) + expf(zz[1] - m));
        out[g * 2 + 0] = zz[0] - lse;
        out[g * 2 + 1] = zz[1] - lse;
    }
}

// ---------------------------------------------------------------------------
extern "C" void kernel_launch(void* const* d_in, const int* in_sizes, int n_in,
                              void* d_out, int out_size)
{
    const float* x     = (const float*)d_in[0];
    const int*   ei    = (const int*)  d_in[1];
    const int*   batch = (const int*)  d_in[2];

    int wi = (in_sizes[3] < 64) ? 4 : 3;
    const float* W[28];
    for (int i = 0; i < 28 && wi + i < n_in; i++) W[i] = (const float*)d_in[wi + i];

    int n_nodes = in_sizes[0] / 128;
    int n_edges = in_sizes[1] / 2;

    float *z, *pool;
    uint2 *hh;
    int *deg, *row, *cur, *col, *bsum;
    cudaGetSymbolAddress((void**)&z,    g_z);
    cudaGetSymbolAddress((void**)&hh,   g_hh);
    cudaGetSymbolAddress((void**)&pool, g_pool);
    cudaGetSymbolAddress((void**)&deg,  g_deg);
    cudaGetSymbolAddress((void**)&row,  g_row);
    cudaGetSymbolAddress((void**)&cur,  g_cur);
    cudaGetSymbolAddress((void**)&col,  g_col);
    cudaGetSymbolAddress((void**)&bsum, g_bsum);

    float* out = (float*)d_out;

    const int SM_GA = (128 * APAD + 64 * BPAD) * 2;   // ~52KB dyn smem
    cudaFuncSetAttribute(gemmA_hmma_kernel,
                         cudaFuncAttributeMaxDynamicSharedMemorySize, SM_GA);

    int mlpBlocks  = (n_nodes + 127) / 128;
    int pullBlocks = (n_nodes * 16 + 255) / 256;
    int scanBlocks = (n_nodes + SCAN_B - 1) / SCAN_B;
    int zeroN      = n_nodes + 1;

    // ---- CSR build; gemmA_hmma is OUR launch #4 (profiled) ----
    zero_both_kernel<<<(zeroN + 255) / 256, 256>>>(deg, zeroN, pool, NGRAPH * 192); // 1
    hist_kernel<<<(n_edges + 255) / 256, 256>>>(ei, deg, n_edges);                  // 2
    bsum_kernel<<<scanBlocks, SCAN_B>>>(deg, bsum, n_nodes);                        // 3
    gemmA_hmma_kernel<<<mlpBlocks, 256, SM_GA>>>(x, W[0], hh, n_nodes);             // 4
    scatter_scan_kernel<<<scanBlocks, SCAN_B>>>(deg, bsum, row, cur, n_nodes);      // 5
    fill_kernel<<<(n_edges + 255) / 256, 256>>>(ei, cur, col, n_edges);             // 6

    // ---- layer 1 ----
    pull64h_kernel<<<pullBlocks, 256>>>(hh, row, col, z, n_nodes);                  // 7
    mlpB_kernel<<<mlpBlocks, 128>>>(z, W[1], W[2], W[3], W[4], W[5], W[6], W[7],
                                    hh, batch, pool, 0, n_nodes);                   // 8

    // ---- layer 2 ----
    pull64h_kernel<<<pullBlocks, 256>>>(hh, row, col, z, n_nodes);                  // 9
    mlp64_kernel<<<mlpBlocks, 128>>>(z, W[8], W[9], W[10], W[11], W[12], W[13], W[14], W[15],
                                     hh, batch, pool, 64, n_nodes);                 // 10

    // ---- layer 3 ----
    pull64h_kernel<<<pullBlocks, 256>>>(hh, row, col, z, n_nodes);                  // 11
    mlp64_kernel<<<mlpBlocks, 128>>>(z, W[16], W[17], W[18], W[19], W[20], W[21], W[22], W[23],
                                     hh, batch, pool, 128, n_nodes);                // 12

    final_kernel<<<NGRAPH, 64>>>(pool, W[24], W[25], W[26], W[27], out);            // 13
}

// round 14
// speedup vs baseline: 1.7037x; 1.4317x over previous
#include <cuda_runtime.h>
#include <cuda_fp16.h>
#include <math.h>

// ---------------------------------------------------------------------------
// GIN (3 GINConv layers + BN + ReLU + MLP head)
//   N_NODES=100000, N_EDGES=1200000, D_IN=128, D_H=64, N_GRAPHS=256
// R13 changes vs R12 (395.8us):
//   * mlpB and mlp64 ported to tensor cores (m16n8k16 f16f16f32), using the
//     fragment scheme validated by gemmA_hmma in R12.
//     - mlpB_hmma: BN+ReLU folded into fp16 A-tile load; one GEMM (w2).
//     - mlp64_hmma: GEMM1(w1) -> BN+ReLU on C fragments -> write h back to
//       As (warp-private rows, conflict-free) -> Bs := w2 -> GEMM2.
//   * pull / CSR / gemmA_hmma / final unchanged.
// ---------------------------------------------------------------------------

#define MAX_NODES 100000
#define MAX_EDGES 1200000
#define NGRAPH    256
#define SCAN_B    1024
#define MAX_SCAN_BLOCKS 128
#define APAD 136                    // halves stride, gemmA A tile (128+8)
#define BPAD 136
#define MPAD 72                     // halves stride, mlp tiles (64+8)

__device__ float g_z   [MAX_NODES * 64];          // fp32 aggregated rows
__device__ uint2 g_hh  [MAX_NODES * 16 + 16];     // fp16 activation rows + pad
__device__ float g_pool[NGRAPH * 192];
__device__ int   g_deg [MAX_NODES + 1];
__device__ int   g_row [MAX_NODES + 1];
__device__ int   g_cur [MAX_NODES];
__device__ int   g_col [MAX_EDGES];
__device__ int   g_bsum[MAX_SCAN_BLOCKS];

__device__ __forceinline__ float4 h2f4(uint2 u) {
    __half2 a = *(__half2*)&u.x, b = *(__half2*)&u.y;
    float2 fa = __half22float2(a), fb = __half22float2(b);
    return make_float4(fa.x, fa.y, fb.x, fb.y);
}

__device__ __forceinline__ void mma16816(float* c,
    unsigned a0, unsigned a1, unsigned a2, unsigned a3,
    unsigned b0, unsigned b1)
{
    asm volatile(
        "mma.sync.aligned.m16n8k16.row.col.f32.f16.f16.f32 "
        "{%0,%1,%2,%3}, {%4,%5,%6,%7}, {%8,%9}, {%0,%1,%2,%3};"
        : "+f"(c[0]), "+f"(c[1]), "+f"(c[2]), "+f"(c[3])
        : "r"(a0), "r"(a1), "r"(a2), "r"(a3), "r"(b0), "r"(b1));
}

// ---------------------------------------------------------------------------
__global__ void zero_both_kernel(int* __restrict__ deg, int nd,
                                 float* __restrict__ pool, int np) {
    int i = blockIdx.x * blockDim.x + threadIdx.x;
    if (i < nd) deg[i] = 0;
    if (i < np) pool[i] = 0.f;
}

// ---------------------------------------------------------------------------
// CSR build
// ---------------------------------------------------------------------------
__global__ void hist_kernel(const int* __restrict__ ei, int* __restrict__ deg, int n_edges) {
    int e = blockIdx.x * blockDim.x + threadIdx.x;
    if (e < n_edges) atomicAdd(deg + __ldg(ei + n_edges + e), 1);
}

__global__ void bsum_kernel(const int* __restrict__ deg, int* __restrict__ bsum, int n) {
    __shared__ int sm[SCAN_B];
    int i = blockIdx.x * SCAN_B + threadIdx.x;
    sm[threadIdx.x] = (i < n) ? deg[i] : 0;
    __syncthreads();
#pragma unroll
    for (int off = SCAN_B / 2; off > 0; off >>= 1) {
        if (threadIdx.x < off) sm[threadIdx.x] += sm[threadIdx.x + off];
        __syncthreads();
    }
    if (threadIdx.x == 0) bsum[blockIdx.x] = sm[0];
}

__global__ void scatter_scan_kernel(const int* __restrict__ deg,
                                    const int* __restrict__ bsum,
                                    int* __restrict__ rowptr, int* __restrict__ cur, int n) {
    __shared__ int sm[SCAN_B];
    __shared__ int boff;
    int bid = blockIdx.x;
    if (threadIdx.x < 32) {
        int s = 0;
        for (int i = threadIdx.x; i < bid; i += 32) s += __ldg(bsum + i);
#pragma unroll
        for (int o = 16; o > 0; o >>= 1) s += __shfl_down_sync(0xffffffffu, s, o);
        if (threadIdx.x == 0) boff = s;
    }
    int i = bid * SCAN_B + threadIdx.x;
    int v = (i < n) ? deg[i] : 0;
    sm[threadIdx.x] = v;
    __syncthreads();
#pragma unroll
    for (int off = 1; off < SCAN_B; off *= 2) {
        int t = (threadIdx.x >= off) ? sm[threadIdx.x - off] : 0;
        __syncthreads();
        sm[threadIdx.x] += t;
        __syncthreads();
    }
    int excl = sm[threadIdx.x] - v + boff;
    if (i < n) { rowptr[i] = excl; cur[i] = excl; }
    if (i == n - 1) rowptr[n] = excl + v;
}

__global__ void fill_kernel(const int* __restrict__ ei, int* __restrict__ cur,
                            int* __restrict__ col, int n_edges) {
    int e = blockIdx.x * blockDim.x + threadIdx.x;
    if (e >= n_edges) return;
    int s = __ldg(ei + e);
    int d = __ldg(ei + n_edges + e);
    int pos = atomicAdd(cur + d, 1);
    col[pos] = s;
}

// ---------------------------------------------------------------------------
// Pull aggregation over fp16 rows (fp32 accumulate, fp32 out). 16 thr/node.
// ---------------------------------------------------------------------------
__global__ void pull64h_kernel(const uint2* __restrict__ hh,
                               const int* __restrict__ rowptr,
                               const int* __restrict__ col,
                               float* __restrict__ zout, int n_nodes) {
    int t = blockIdx.x * blockDim.x + threadIdx.x;
    int node = t >> 4, lane = t & 15;
    if (node >= n_nodes) return;
    float4 acc = h2f4(__ldg(hh + (size_t)node * 16 + lane));
    int e   = __ldg(rowptr + node);
    int end = __ldg(rowptr + node + 1);
    for (; e + 8 <= end; e += 8) {
        int s0 = __ldg(col + e),     s1 = __ldg(col + e + 1);
        int s2 = __ldg(col + e + 2), s3 = __ldg(col + e + 3);
        int s4 = __ldg(col + e + 4), s5 = __ldg(col + e + 5);
        int s6 = __ldg(col + e + 6), s7 = __ldg(col + e + 7);
        float4 v0 = h2f4(__ldg(hh + (size_t)s0 * 16 + lane));
        float4 v1 = h2f4(__ldg(hh + (size_t)s1 * 16 + lane));
        float4 v2 = h2f4(__ldg(hh + (size_t)s2 * 16 + lane));
        float4 v3 = h2f4(__ldg(hh + (size_t)s3 * 16 + lane));
        float4 v4 = h2f4(__ldg(hh + (size_t)s4 * 16 + lane));
        float4 v5 = h2f4(__ldg(hh + (size_t)s5 * 16 + lane));
        float4 v6 = h2f4(__ldg(hh + (size_t)s6 * 16 + lane));
        float4 v7 = h2f4(__ldg(hh + (size_t)s7 * 16 + lane));
        acc.x += ((v0.x + v1.x) + (v2.x + v3.x)) + ((v4.x + v5.x) + (v6.x + v7.x));
        acc.y += ((v0.y + v1.y) + (v2.y + v3.y)) + ((v4.y + v5.y) + (v6.y + v7.y));
        acc.z += ((v0.z + v1.z) + (v2.z + v3.z)) + ((v4.z + v5.z) + (v6.z + v7.z));
        acc.w += ((v0.w + v1.w) + (v2.w + v3.w)) + ((v4.w + v5.w) + (v6.w + v7.w));
    }
    for (; e + 4 <= end; e += 4) {
        int s0 = __ldg(col + e),     s1 = __ldg(col + e + 1);
        int s2 = __ldg(col + e + 2), s3 = __ldg(col + e + 3);
        float4 v0 = h2f4(__ldg(hh + (size_t)s0 * 16 + lane));
        float4 v1 = h2f4(__ldg(hh + (size_t)s1 * 16 + lane));
        float4 v2 = h2f4(__ldg(hh + (size_t)s2 * 16 + lane));
        float4 v3 = h2f4(__ldg(hh + (size_t)s3 * 16 + lane));
        acc.x += (v0.x + v1.x) + (v2.x + v3.x);
        acc.y += (v0.y + v1.y) + (v2.y + v3.y);
        acc.z += (v0.z + v1.z) + (v2.z + v3.z);
        acc.w += (v0.w + v1.w) + (v2.w + v3.w);
    }
    for (; e < end; e++) {
        int s = __ldg(col + e);
        float4 v = h2f4(__ldg(hh + (size_t)s * 16 + lane));
        acc.x += v.x; acc.y += v.y; acc.z += v.z; acc.w += v.w;
    }
    ((float4*)zout)[(size_t)node * 16 + lane] = acc;
}

// ---------------------------------------------------------------------------
// gemmA_hmma: hh = fp16(x @ w1) on tensor cores. (unchanged from R12)
// ---------------------------------------------------------------------------
__global__ __launch_bounds__(256) void gemmA_hmma_kernel(
    const float* __restrict__ x, const float* __restrict__ w1,
    uint2* __restrict__ hh, int n_nodes)
{
    extern __shared__ __half dsm[];
    __half* As = dsm;                  // [128][APAD]
    __half* Bs = dsm + 128 * APAD;     // [64][BPAD]
    int tid = threadIdx.x;
    int nbase = blockIdx.x * 128;

    for (int i4 = tid; i4 < 4096; i4 += 256) {
        int row = i4 >> 5, k4 = i4 & 31;
        int gn = nbase + row; if (gn >= n_nodes) gn = n_nodes - 1;
        float4 v = __ldg((const float4*)(x + (size_t)gn * 128) + k4);
        __half2 h0 = __floats2half2_rn(v.x, v.y);
        __half2 h1 = __floats2half2_rn(v.z, v.w);
        unsigned* dst = (unsigned*)&As[row * APAD + k4 * 4];
        dst[0] = *(unsigned*)&h0;
        dst[1] = *(unsigned*)&h1;
    }
    for (int i = tid; i < 128 * 64; i += 256) {
        int k = i >> 6, n = i & 63;
        Bs[n * BPAD + k] = __float2half(__ldg(w1 + i));
    }
    __syncthreads();

    int wid = tid >> 5, lane = tid & 31;
    int r0 = wid * 16 + (lane >> 2);
    int kp = (lane & 3) * 2;

    float c[8][4];
#pragma unroll
    for (int nt = 0; nt < 8; nt++)
#pragma unroll
        for (int j = 0; j < 4; j++) c[nt][j] = 0.f;

#pragma unroll
    for (int kt = 0; kt < 8; kt++) {
        int kb = kt * 16 + kp;
        unsigned a0 = *(unsigned*)&As[r0 * APAD + kb];
        unsigned a1 = *(unsigned*)&As[(r0 + 8) * APAD + kb];
        unsigned a2 = *(unsigned*)&As[r0 * APAD + kb + 8];
        unsigned a3 = *(unsigned*)&As[(r0 + 8) * APAD + kb + 8];
#pragma unroll
        for (int nt = 0; nt < 8; nt++) {
            int n = nt * 8 + (lane >> 2);
            unsigned b0 = *(unsigned*)&Bs[n * BPAD + kb];
            unsigned b1 = *(unsigned*)&Bs[n * BPAD + kb + 8];
            mma16816(c[nt], a0, a1, a2, a3, b0, b1);
        }
    }

    int colp = (lane & 3) * 2;
#pragma unroll
    for (int rr = 0; rr < 2; rr++) {
        int node = nbase + r0 + rr * 8;
        if (node >= n_nodes) continue;
        __half* hrow = (__half*)(hh + (size_t)node * 16);
#pragma unroll
        for (int nt = 0; nt < 8; nt++) {
            __half2 hv = __floats2half2_rn(c[nt][rr * 2 + 0], c[nt][rr * 2 + 1]);
            *(unsigned*)&hrow[nt * 8 + colp] = *(unsigned*)&hv;
        }
    }
}

// ---------------------------------------------------------------------------
// mlpB_hmma (layer-1 tail): h = relu( relu(BN(z+b1)) @ w2 + b2 ).
// BN+ReLU folded into fp16 A-tile load; one HMMA GEMM with w2.
// ---------------------------------------------------------------------------
__global__ __launch_bounds__(256) void mlpB_hmma_kernel(
    const float* __restrict__ z,
    const float* __restrict__ b1,
    const float* __restrict__ gg, const float* __restrict__ bt,
    const float* __restrict__ rm, const float* __restrict__ rv,
    const float* __restrict__ w2, const float* __restrict__ b2,
    uint2*       __restrict__ hh,
    const int*   __restrict__ batch,
    float*       __restrict__ pool, int pool_off, int n_nodes)
{
    __shared__ __half As[128 * MPAD];
    __shared__ __half Bs[64 * MPAD];
    __shared__ float2 scsh[64];
    int tid = threadIdx.x;
    int nbase = blockIdx.x * 128;

    if (tid < 64) {
        float sc = __ldg(gg + tid) * rsqrtf(__ldg(rv + tid) + 1e-5f);
        float sh = (__ldg(b1 + tid) - __ldg(rm + tid)) * sc + __ldg(bt + tid);
        scsh[tid] = make_float2(sc, sh);
    }
    for (int i = tid; i < 64 * 64; i += 256) {
        int k = i >> 6, n = i & 63;
        Bs[n * MPAD + k] = __float2half(__ldg(w2 + i));
    }
    __syncthreads();    // scsh visible for the BN-folded load

    for (int i4 = tid; i4 < 2048; i4 += 256) {
        int row = i4 >> 4, k4 = i4 & 15;
        int gn = nbase + row; if (gn >= n_nodes) gn = n_nodes - 1;
        float4 v = __ldg((const float4*)(z + (size_t)gn * 64) + k4);
        int k = k4 * 4;
        float2 s0 = scsh[k], s1 = scsh[k + 1], s2 = scsh[k + 2], s3 = scsh[k + 3];
        float h0 = fmaxf(fmaf(v.x, s0.x, s0.y), 0.f);
        float h1 = fmaxf(fmaf(v.y, s1.x, s1.y), 0.f);
        float h2v = fmaxf(fmaf(v.z, s2.x, s2.y), 0.f);
        float h3 = fmaxf(fmaf(v.w, s3.x, s3.y), 0.f);
        __half2 p0 = __floats2half2_rn(h0, h1), p1 = __floats2half2_rn(h2v, h3);
        unsigned* dst = (unsigned*)&As[row * MPAD + k];
        dst[0] = *(unsigned*)&p0;
        dst[1] = *(unsigned*)&p1;
    }
    __syncthreads();

    int wid = tid >> 5, lane = tid & 31;
    int r0 = wid * 16 + (lane >> 2);
    int kp = (lane & 3) * 2;

    float c[8][4];
#pragma unroll
    for (int nt = 0; nt < 8; nt++)
#pragma unroll
        for (int j = 0; j < 4; j++) c[nt][j] = 0.f;

#pragma unroll
    for (int kt = 0; kt < 4; kt++) {
        int kb = kt * 16 + kp;
        unsigned a0 = *(unsigned*)&As[r0 * MPAD + kb];
        unsigned a1 = *(unsigned*)&As[(r0 + 8) * MPAD + kb];
        unsigned a2 = *(unsigned*)&As[r0 * MPAD + kb + 8];
        unsigned a3 = *(unsigned*)&As[(r0 + 8) * MPAD + kb + 8];
#pragma unroll
        for (int nt = 0; nt < 8; nt++) {
            int n = nt * 8 + (lane >> 2);
            unsigned b0 = *(unsigned*)&Bs[n * MPAD + kb];
            unsigned b1 = *(unsigned*)&Bs[n * MPAD + kb + 8];
            mma16816(c[nt], a0, a1, a2, a3, b0, b1);
        }
    }

    int colp = (lane & 3) * 2;
#pragma unroll
    for (int rr = 0; rr < 2; rr++) {
        int node = nbase + r0 + rr * 8;
        if (node >= n_nodes) continue;
        __half* hrow = (__half*)(hh + (size_t)node * 16);
        float*  prow = pool + (size_t)__ldg(batch + node) * 192 + pool_off;
#pragma unroll
        for (int nt = 0; nt < 8; nt++) {
            int cA = nt * 8 + colp;
            float v0 = fmaxf(c[nt][rr * 2 + 0] + __ldg(b2 + cA), 0.f);
            float v1 = fmaxf(c[nt][rr * 2 + 1] + __ldg(b2 + cA + 1), 0.f);
            __half2 hv = __floats2half2_rn(v0, v1);
            *(unsigned*)&hrow[cA] = *(unsigned*)&hv;
            asm volatile("red.global.add.v2.f32 [%0], {%1,%2};"
                         :: "l"(prow + cA), "f"(v0), "f"(v1) : "memory");
        }
    }
}

// ---------------------------------------------------------------------------
// mlp64_hmma (layers 2/3): h = relu( relu(BN(z@w1+b1)) @ w2 + b2 ).
// GEMM1 -> BN+ReLU on fragments -> write h back to As (warp-private rows)
// -> Bs := w2 -> GEMM2 -> epilogue.
// ---------------------------------------------------------------------------
__global__ __launch_bounds__(256) void mlp64_hmma_kernel(
    const float* __restrict__ z,
    const float* __restrict__ w1, const float* __restrict__ b1,
    const float* __restrict__ gg, const float* __restrict__ bt,
    const float* __restrict__ rm, const float* __restrict__ rv,
    const float* __restrict__ w2, const float* __restrict__ b2,
    uint2*       __restrict__ hh,
    const int*   __restrict__ batch,
    float*       __restrict__ pool, int pool_off, int n_nodes)
{
    __shared__ __half As[128 * MPAD];
    __shared__ __half Bs[64 * MPAD];
    __shared__ float2 scsh[64];
    int tid = threadIdx.x;
    int nbase = blockIdx.x * 128;

    if (tid < 64) {
        float sc = __ldg(gg + tid) * rsqrtf(__ldg(rv + tid) + 1e-5f);
        float sh = (__ldg(b1 + tid) - __ldg(rm + tid)) * sc + __ldg(bt + tid);
        scsh[tid] = make_float2(sc, sh);
    }
    for (int i = tid; i < 64 * 64; i += 256) {
        int k = i >> 6, n = i & 63;
        Bs[n * MPAD + k] = __float2half(__ldg(w1 + i));
    }
    for (int i4 = tid; i4 < 2048; i4 += 256) {
        int row = i4 >> 4, k4 = i4 & 15;
        int gn = nbase + row; if (gn >= n_nodes) gn = n_nodes - 1;
        float4 v = __ldg((const float4*)(z + (size_t)gn * 64) + k4);
        __half2 p0 = __floats2half2_rn(v.x, v.y), p1 = __floats2half2_rn(v.z, v.w);
        unsigned* dst = (unsigned*)&As[row * MPAD + k4 * 4];
        dst[0] = *(unsigned*)&p0;
        dst[1] = *(unsigned*)&p1;
    }
    __syncthreads();

    int wid = tid >> 5, lane = tid & 31;
    int r0 = wid * 16 + (lane >> 2);
    int kp = (lane & 3) * 2;
    int colp = (lane & 3) * 2;

    // ---- GEMM1 (w1) ----
    float c[8][4];
#pragma unroll
    for (int nt = 0; nt < 8; nt++)
#pragma unroll
        for (int j = 0; j < 4; j++) c[nt][j] = 0.f;

#pragma unroll
    for (int kt = 0; kt < 4; kt++) {
        int kb = kt * 16 + kp;
        unsigned a0 = *(unsigned*)&As[r0 * MPAD + kb];
        unsigned a1 = *(unsigned*)&As[(r0 + 8) * MPAD + kb];
        unsigned a2 = *(unsigned*)&As[r0 * MPAD + kb + 8];
        unsigned a3 = *(unsigned*)&As[(r0 + 8) * MPAD + kb + 8];
#pragma unroll
        for (int nt = 0; nt < 8; nt++) {
            int n = nt * 8 + (lane >> 2);
            unsigned b0 = *(unsigned*)&Bs[n * MPAD + kb];
            unsigned b1 = *(unsigned*)&Bs[n * MPAD + kb + 8];
            mma16816(c[nt], a0, a1, a2, a3, b0, b1);
        }
    }

    // ---- BN + ReLU on fragments -> write h back into As (own rows only).
    // NOTE: warp w reads As rows [w*16, w*16+16) in GEMM1 and writes the same
    // rows here; GEMM1 consumed all its As reads already (register frags).
#pragma unroll
    for (int nt = 0; nt < 8; nt++) {
        int cA = nt * 8 + colp, cB = cA + 1;
        float2 sA = scsh[cA], sB = scsh[cB];
        float h00 = fmaxf(fmaf(c[nt][0], sA.x, sA.y), 0.f);
        float h01 = fmaxf(fmaf(c[nt][1], sB.x, sB.y), 0.f);
        float h10 = fmaxf(fmaf(c[nt][2], sA.x, sA.y), 0.f);
        float h11 = fmaxf(fmaf(c[nt][3], sB.x, sB.y), 0.f);
        __half2 p0 = __floats2half2_rn(h00, h01);
        __half2 p1 = __floats2half2_rn(h10, h11);
        *(unsigned*)&As[r0 * MPAD + cA]       = *(unsigned*)&p0;
        *(unsigned*)&As[(r0 + 8) * MPAD + cA] = *(unsigned*)&p1;
    }
    __syncthreads();   // all warps done reading Bs(w1) + writing their As rows

    for (int i = tid; i < 64 * 64; i += 256) {
        int k = i >> 6, n = i & 63;
        Bs[n * MPAD + k] = __float2half(__ldg(w2 + i));
    }
    __syncthreads();

    // ---- GEMM2 (w2) ----
#pragma unroll
    for (int nt = 0; nt < 8; nt++)
#pragma unroll
        for (int j = 0; j < 4; j++) c[nt][j] = 0.f;

#pragma unroll
    for (int kt = 0; kt < 4; kt++) {
        int kb = kt * 16 + kp;
        unsigned a0 = *(unsigned*)&As[r0 * MPAD + kb];
        unsigned a1 = *(unsigned*)&As[(r0 + 8) * MPAD + kb];
        unsigned a2 = *(unsigned*)&As[r0 * MPAD + kb + 8];
        unsigned a3 = *(unsigned*)&As[(r0 + 8) * MPAD + kb + 8];
#pragma unroll
        for (int nt = 0; nt < 8; nt++) {
            int n = nt * 8 + (lane >> 2);
            unsigned b0 = *(unsigned*)&Bs[n * MPAD + kb];
            unsigned b1 = *(unsigned*)&Bs[n * MPAD + kb + 8];
            mma16816(c[nt], a0, a1, a2, a3, b0, b1);
        }
    }

    // ---- epilogue ----
#pragma unroll
    for (int rr = 0; rr < 2; rr++) {
        int node = nbase + r0 + rr * 8;
        if (node >= n_nodes) continue;
        __half* hrow = (__half*)(hh + (size_t)node * 16);
        float*  prow = pool + (size_t)__ldg(batch + node) * 192 + pool_off;
#pragma unroll
        for (int nt = 0; nt < 8; nt++) {
            int cA = nt * 8 + colp;
            float v0 = fmaxf(c[nt][rr * 2 + 0] + __ldg(b2 + cA), 0.f);
            float v1 = fmaxf(c[nt][rr * 2 + 1] + __ldg(b2 + cA + 1), 0.f);
            __half2 hv = __floats2half2_rn(v0, v1);
            *(unsigned*)&hrow[cA] = *(unsigned*)&hv;
            asm volatile("red.global.add.v2.f32 [%0], {%1,%2};"
                         :: "l"(prow + cA), "f"(v0), "f"(v1) : "memory");
        }
    }
}

// ---------------------------------------------------------------------------
__global__ void final_kernel(const float* __restrict__ pool,
                             const float* __restrict__ lw1, const float* __restrict__ lb1,
                             const float* __restrict__ lw2, const float* __restrict__ lb2,
                             float* __restrict__ out)
{
    __shared__ float prow[192];
    __shared__ float hid[64];
    __shared__ float zz[2];
    int g = blockIdx.x, j = threadIdx.x;
    for (int k = j; k < 192; k += 64) prow[k] = pool[g * 192 + k];
    __syncthreads();
    float a = __ldg(lb1 + j);
    for (int k = 0; k < 192; k++) a = fmaf(prow[k], __ldg(lw1 + k * 64 + j), a);
    hid[j] = fmaxf(a, 0.f);
    __syncthreads();
    if (j < 2) {
        float zv = __ldg(lb2 + j);
#pragma unroll 8
        for (int k = 0; k < 64; k++) zv = fmaf(hid[k], __ldg(lw2 + k * 2 + j), zv);
        zz[j] = zv;
    }
    __syncthreads();
    if (j == 0) {
        float m   = fmaxf(zz[0], zz[1]);
        float lse = m + logf(expf(zz[0] - m) + expf(zz[1] - m));
        out[g * 2 + 0] = zz[0] - lse;
        out[g * 2 + 1] = zz[1] - lse;
    }
}

// ---------------------------------------------------------------------------
extern "C" void kernel_launch(void* const* d_in, const int* in_sizes, int n_in,
                              void* d_out, int out_size)
{
    const float* x     = (const float*)d_in[0];
    const int*   ei    = (const int*)  d_in[1];
    const int*   batch = (const int*)  d_in[2];

    int wi = (in_sizes[3] < 64) ? 4 : 3;
    const float* W[28];
    for (int i = 0; i < 28 && wi + i < n_in; i++) W[i] = (const float*)d_in[wi + i];

    int n_nodes = in_sizes[0] / 128;
    int n_edges = in_sizes[1] / 2;

    float *z, *pool;
    uint2 *hh;
    int *deg, *row, *cur, *col, *bsum;
    cudaGetSymbolAddress((void**)&z,    g_z);
    cudaGetSymbolAddress((void**)&hh,   g_hh);
    cudaGetSymbolAddress((void**)&pool, g_pool);
    cudaGetSymbolAddress((void**)&deg,  g_deg);
    cudaGetSymbolAddress((void**)&row,  g_row);
    cudaGetSymbolAddress((void**)&cur,  g_cur);
    cudaGetSymbolAddress((void**)&col,  g_col);
    cudaGetSymbolAddress((void**)&bsum, g_bsum);

    float* out = (float*)d_out;

    const int SM_GA = (128 * APAD + 64 * BPAD) * 2;   // ~52KB dyn smem (gemmA)
    cudaFuncSetAttribute(gemmA_hmma_kernel,
                         cudaFuncAttributeMaxDynamicSharedMemorySize, SM_GA);

    int mlpBlocks  = (n_nodes + 127) / 128;
    int pullBlocks = (n_nodes * 16 + 255) / 256;
    int scanBlocks = (n_nodes + SCAN_B - 1) / SCAN_B;
    int zeroN      = n_nodes + 1;

    // ---- CSR build; gemmA_hmma is OUR launch #4 (profiled) ----
    zero_both_kernel<<<(zeroN + 255) / 256, 256>>>(deg, zeroN, pool, NGRAPH * 192); // 1
    hist_kernel<<<(n_edges + 255) / 256, 256>>>(ei, deg, n_edges);                  // 2
    bsum_kernel<<<scanBlocks, SCAN_B>>>(deg, bsum, n_nodes);                        // 3
    gemmA_hmma_kernel<<<mlpBlocks, 256, SM_GA>>>(x, W[0], hh, n_nodes);             // 4
    scatter_scan_kernel<<<scanBlocks, SCAN_B>>>(deg, bsum, row, cur, n_nodes);      // 5
    fill_kernel<<<(n_edges + 255) / 256, 256>>>(ei, cur, col, n_edges);             // 6

    // ---- layer 1 ----
    pull64h_kernel<<<pullBlocks, 256>>>(hh, row, col, z, n_nodes);                  // 7
    mlpB_hmma_kernel<<<mlpBlocks, 256>>>(z, W[1], W[2], W[3], W[4], W[5], W[6], W[7],
                                         hh, batch, pool, 0, n_nodes);              // 8

    // ---- layer 2 ----
    pull64h_kernel<<<pullBlocks, 256>>>(hh, row, col, z, n_nodes);                  // 9
    mlp64_hmma_kernel<<<mlpBlocks, 256>>>(z, W[8], W[9], W[10], W[11], W[12], W[13], W[14], W[15],
                                          hh, batch, pool, 64, n_nodes);            // 10

    // ---- layer 3 ----
    pull64h_kernel<<<pullBlocks, 256>>>(hh, row, col, z, n_nodes);                  // 11
    mlp64_hmma_kernel<<<mlpBlocks, 256>>>(z, W[16], W[17], W[18], W[19], W[20], W[21], W[22], W[23],
                                          hh, batch, pool, 128, n_nodes);           // 12

    final_kernel<<<NGRAPH, 64>>>(pool, W[24], W[25], W[26], W[27], out);            // 13
}

// round 15
// speedup vs baseline: 1.7832x; 1.0466x over previous
#include <cuda_runtime.h>
#include <cuda_fp16.h>
#include <math.h>

// ---------------------------------------------------------------------------
// GIN (3 GINConv layers + BN + ReLU + MLP head)
//   N_NODES=100000, N_EDGES=1200000, D_IN=128, D_H=64, N_GRAPHS=256
// R14 changes vs R13 (276.5us):
//   * z stored as fp16 (zh): pull write stream halved, mlp read stream
//     halved. mlp64's A-tile load becomes a raw uint4 copy (no converts).
//     Layers 2/3: numerically IDENTICAL (z was quantized to fp16 at the
//     GEMM input anyway). Layer 1: BN input now fp16-rounded (negligible).
//   * all kernels otherwise byte-identical to R13.
// ---------------------------------------------------------------------------

#define MAX_NODES 100000
#define MAX_EDGES 1200000
#define NGRAPH    256
#define SCAN_B    1024
#define MAX_SCAN_BLOCKS 128
#define APAD 136                    // halves stride, gemmA A tile (128+8)
#define BPAD 136
#define MPAD 72                     // halves stride, mlp tiles (64+8)

__device__ uint2 g_zh  [MAX_NODES * 16 + 16];     // fp16 aggregated rows
__device__ uint2 g_hh  [MAX_NODES * 16 + 16];     // fp16 activation rows
__device__ float g_pool[NGRAPH * 192];
__device__ int   g_deg [MAX_NODES + 1];
__device__ int   g_row [MAX_NODES + 1];
__device__ int   g_cur [MAX_NODES];
__device__ int   g_col [MAX_EDGES];
__device__ int   g_bsum[MAX_SCAN_BLOCKS];

__device__ __forceinline__ float4 h2f4(uint2 u) {
    __half2 a = *(__half2*)&u.x, b = *(__half2*)&u.y;
    float2 fa = __half22float2(a), fb = __half22float2(b);
    return make_float4(fa.x, fa.y, fb.x, fb.y);
}
__device__ __forceinline__ uint2 f4h(float a, float b, float c, float d) {
    __half2 lo = __floats2half2_rn(a, b), hi = __floats2half2_rn(c, d);
    uint2 u; u.x = *(unsigned*)&lo; u.y = *(unsigned*)&hi; return u;
}

__device__ __forceinline__ void mma16816(float* c,
    unsigned a0, unsigned a1, unsigned a2, unsigned a3,
    unsigned b0, unsigned b1)
{
    asm volatile(
        "mma.sync.aligned.m16n8k16.row.col.f32.f16.f16.f32 "
        "{%0,%1,%2,%3}, {%4,%5,%6,%7}, {%8,%9}, {%0,%1,%2,%3};"
        : "+f"(c[0]), "+f"(c[1]), "+f"(c[2]), "+f"(c[3])
        : "r"(a0), "r"(a1), "r"(a2), "r"(a3), "r"(b0), "r"(b1));
}

// ---------------------------------------------------------------------------
__global__ void zero_both_kernel(int* __restrict__ deg, int nd,
                                 float* __restrict__ pool, int np) {
    int i = blockIdx.x * blockDim.x + threadIdx.x;
    if (i < nd) deg[i] = 0;
    if (i < np) pool[i] = 0.f;
}

// ---------------------------------------------------------------------------
// CSR build
// ---------------------------------------------------------------------------
__global__ void hist_kernel(const int* __restrict__ ei, int* __restrict__ deg, int n_edges) {
    int e = blockIdx.x * blockDim.x + threadIdx.x;
    if (e < n_edges) atomicAdd(deg + __ldg(ei + n_edges + e), 1);
}

__global__ void bsum_kernel(const int* __restrict__ deg, int* __restrict__ bsum, int n) {
    __shared__ int sm[SCAN_B];
    int i = blockIdx.x * SCAN_B + threadIdx.x;
    sm[threadIdx.x] = (i < n) ? deg[i] : 0;
    __syncthreads();
#pragma unroll
    for (int off = SCAN_B / 2; off > 0; off >>= 1) {
        if (threadIdx.x < off) sm[threadIdx.x] += sm[threadIdx.x + off];
        __syncthreads();
    }
    if (threadIdx.x == 0) bsum[blockIdx.x] = sm[0];
}

__global__ void scatter_scan_kernel(const int* __restrict__ deg,
                                    const int* __restrict__ bsum,
                                    int* __restrict__ rowptr, int* __restrict__ cur, int n) {
    __shared__ int sm[SCAN_B];
    __shared__ int boff;
    int bid = blockIdx.x;
    if (threadIdx.x < 32) {
        int s = 0;
        for (int i = threadIdx.x; i < bid; i += 32) s += __ldg(bsum + i);
#pragma unroll
        for (int o = 16; o > 0; o >>= 1) s += __shfl_down_sync(0xffffffffu, s, o);
        if (threadIdx.x == 0) boff = s;
    }
    int i = bid * SCAN_B + threadIdx.x;
    int v = (i < n) ? deg[i] : 0;
    sm[threadIdx.x] = v;
    __syncthreads();
#pragma unroll
    for (int off = 1; off < SCAN_B; off *= 2) {
        int t = (threadIdx.x >= off) ? sm[threadIdx.x - off] : 0;
        __syncthreads();
        sm[threadIdx.x] += t;
        __syncthreads();
    }
    int excl = sm[threadIdx.x] - v + boff;
    if (i < n) { rowptr[i] = excl; cur[i] = excl; }
    if (i == n - 1) rowptr[n] = excl + v;
}

__global__ void fill_kernel(const int* __restrict__ ei, int* __restrict__ cur,
                            int* __restrict__ col, int n_edges) {
    int e = blockIdx.x * blockDim.x + threadIdx.x;
    if (e >= n_edges) return;
    int s = __ldg(ei + e);
    int d = __ldg(ei + n_edges + e);
    int pos = atomicAdd(cur + d, 1);
    col[pos] = s;
}

// ---------------------------------------------------------------------------
// Pull aggregation over fp16 rows; fp32 accumulate; **fp16 output**.
// 16 thr/node, lane handles 4 values (uint2 in, uint2 out).
// ---------------------------------------------------------------------------
__global__ void pull64h_kernel(const uint2* __restrict__ hh,
                               const int* __restrict__ rowptr,
                               const int* __restrict__ col,
                               uint2* __restrict__ zh, int n_nodes) {
    int t = blockIdx.x * blockDim.x + threadIdx.x;
    int node = t >> 4, lane = t & 15;
    if (node >= n_nodes) return;
    float4 acc = h2f4(__ldg(hh + (size_t)node * 16 + lane));
    int e   = __ldg(rowptr + node);
    int end = __ldg(rowptr + node + 1);
    for (; e + 8 <= end; e += 8) {
        int s0 = __ldg(col + e),     s1 = __ldg(col + e + 1);
        int s2 = __ldg(col + e + 2), s3 = __ldg(col + e + 3);
        int s4 = __ldg(col + e + 4), s5 = __ldg(col + e + 5);
        int s6 = __ldg(col + e + 6), s7 = __ldg(col + e + 7);
        float4 v0 = h2f4(__ldg(hh + (size_t)s0 * 16 + lane));
        float4 v1 = h2f4(__ldg(hh + (size_t)s1 * 16 + lane));
        float4 v2 = h2f4(__ldg(hh + (size_t)s2 * 16 + lane));
        float4 v3 = h2f4(__ldg(hh + (size_t)s3 * 16 + lane));
        float4 v4 = h2f4(__ldg(hh + (size_t)s4 * 16 + lane));
        float4 v5 = h2f4(__ldg(hh + (size_t)s5 * 16 + lane));
        float4 v6 = h2f4(__ldg(hh + (size_t)s6 * 16 + lane));
        float4 v7 = h2f4(__ldg(hh + (size_t)s7 * 16 + lane));
        acc.x += ((v0.x + v1.x) + (v2.x + v3.x)) + ((v4.x + v5.x) + (v6.x + v7.x));
        acc.y += ((v0.y + v1.y) + (v2.y + v3.y)) + ((v4.y + v5.y) + (v6.y + v7.y));
        acc.z += ((v0.z + v1.z) + (v2.z + v3.z)) + ((v4.z + v5.z) + (v6.z + v7.z));
        acc.w += ((v0.w + v1.w) + (v2.w + v3.w)) + ((v4.w + v5.w) + (v6.w + v7.w));
    }
    for (; e + 4 <= end; e += 4) {
        int s0 = __ldg(col + e),     s1 = __ldg(col + e + 1);
        int s2 = __ldg(col + e + 2), s3 = __ldg(col + e + 3);
        float4 v0 = h2f4(__ldg(hh + (size_t)s0 * 16 + lane));
        float4 v1 = h2f4(__ldg(hh + (size_t)s1 * 16 + lane));
        float4 v2 = h2f4(__ldg(hh + (size_t)s2 * 16 + lane));
        float4 v3 = h2f4(__ldg(hh + (size_t)s3 * 16 + lane));
        acc.x += (v0.x + v1.x) + (v2.x + v3.x);
        acc.y += (v0.y + v1.y) + (v2.y + v3.y);
        acc.z += (v0.z + v1.z) + (v2.z + v3.z);
        acc.w += (v0.w + v1.w) + (v2.w + v3.w);
    }
    for (; e < end; e++) {
        int s = __ldg(col + e);
        float4 v = h2f4(__ldg(hh + (size_t)s * 16 + lane));
        acc.x += v.x; acc.y += v.y; acc.z += v.z; acc.w += v.w;
    }
    zh[(size_t)node * 16 + lane] = f4h(acc.x, acc.y, acc.z, acc.w);
}

// ---------------------------------------------------------------------------
// gemmA_hmma: hh = fp16(x @ w1) on tensor cores. (unchanged from R12/R13)
// ---------------------------------------------------------------------------
__global__ __launch_bounds__(256) void gemmA_hmma_kernel(
    const float* __restrict__ x, const float* __restrict__ w1,
    uint2* __restrict__ hh, int n_nodes)
{
    extern __shared__ __half dsm[];
    __half* As = dsm;                  // [128][APAD]
    __half* Bs = dsm + 128 * APAD;     // [64][BPAD]
    int tid = threadIdx.x;
    int nbase = blockIdx.x * 128;

    for (int i4 = tid; i4 < 4096; i4 += 256) {
        int row = i4 >> 5, k4 = i4 & 31;
        int gn = nbase + row; if (gn >= n_nodes) gn = n_nodes - 1;
        float4 v = __ldg((const float4*)(x + (size_t)gn * 128) + k4);
        __half2 h0 = __floats2half2_rn(v.x, v.y);
        __half2 h1 = __floats2half2_rn(v.z, v.w);
        unsigned* dst = (unsigned*)&As[row * APAD + k4 * 4];
        dst[0] = *(unsigned*)&h0;
        dst[1] = *(unsigned*)&h1;
    }
    for (int i = tid; i < 128 * 64; i += 256) {
        int k = i >> 6, n = i & 63;
        Bs[n * BPAD + k] = __float2half(__ldg(w1 + i));
    }
    __syncthreads();

    int wid = tid >> 5, lane = tid & 31;
    int r0 = wid * 16 + (lane >> 2);
    int kp = (lane & 3) * 2;

    float c[8][4];
#pragma unroll
    for (int nt = 0; nt < 8; nt++)
#pragma unroll
        for (int j = 0; j < 4; j++) c[nt][j] = 0.f;

#pragma unroll
    for (int kt = 0; kt < 8; kt++) {
        int kb = kt * 16 + kp;
        unsigned a0 = *(unsigned*)&As[r0 * APAD + kb];
        unsigned a1 = *(unsigned*)&As[(r0 + 8) * APAD + kb];
        unsigned a2 = *(unsigned*)&As[r0 * APAD + kb + 8];
        unsigned a3 = *(unsigned*)&As[(r0 + 8) * APAD + kb + 8];
#pragma unroll
        for (int nt = 0; nt < 8; nt++) {
            int n = nt * 8 + (lane >> 2);
            unsigned b0 = *(unsigned*)&Bs[n * BPAD + kb];
            unsigned b1 = *(unsigned*)&Bs[n * BPAD + kb + 8];
            mma16816(c[nt], a0, a1, a2, a3, b0, b1);
        }
    }

    int colp = (lane & 3) * 2;
#pragma unroll
    for (int rr = 0; rr < 2; rr++) {
        int node = nbase + r0 + rr * 8;
        if (node >= n_nodes) continue;
        __half* hrow = (__half*)(hh + (size_t)node * 16);
#pragma unroll
        for (int nt = 0; nt < 8; nt++) {
            __half2 hv = __floats2half2_rn(c[nt][rr * 2 + 0], c[nt][rr * 2 + 1]);
            *(unsigned*)&hrow[nt * 8 + colp] = *(unsigned*)&hv;
        }
    }
}

// ---------------------------------------------------------------------------
// mlpB_hmma (layer-1 tail): h = relu( relu(BN(zh+b1)) @ w2 + b2 ).
// zh is fp16; BN+ReLU folded into the A-tile load.
// ---------------------------------------------------------------------------
__global__ __launch_bounds__(256) void mlpB_hmma_kernel(
    const uint2* __restrict__ zh,
    const float* __restrict__ b1,
    const float* __restrict__ gg, const float* __restrict__ bt,
    const float* __restrict__ rm, const float* __restrict__ rv,
    const float* __restrict__ w2, const float* __restrict__ b2,
    uint2*       __restrict__ hh,
    const int*   __restrict__ batch,
    float*       __restrict__ pool, int pool_off, int n_nodes)
{
    __shared__ __half As[128 * MPAD];
    __shared__ __half Bs[64 * MPAD];
    __shared__ float2 scsh[64];
    int tid = threadIdx.x;
    int nbase = blockIdx.x * 128;

    if (tid < 64) {
        float sc = __ldg(gg + tid) * rsqrtf(__ldg(rv + tid) + 1e-5f);
        float sh = (__ldg(b1 + tid) - __ldg(rm + tid)) * sc + __ldg(bt + tid);
        scsh[tid] = make_float2(sc, sh);
    }
    for (int i = tid; i < 64 * 64; i += 256) {
        int k = i >> 6, n = i & 63;
        Bs[n * MPAD + k] = __float2half(__ldg(w2 + i));
    }
    __syncthreads();    // scsh visible for the BN-folded load

    for (int i4 = tid; i4 < 2048; i4 += 256) {
        int row = i4 >> 4, k4 = i4 & 15;
        int gn = nbase + row; if (gn >= n_nodes) gn = n_nodes - 1;
        float4 v = h2f4(__ldg(zh + (size_t)gn * 16 + k4));
        int k = k4 * 4;
        float2 s0 = scsh[k], s1 = scsh[k + 1], s2 = scsh[k + 2], s3 = scsh[k + 3];
        float h0 = fmaxf(fmaf(v.x, s0.x, s0.y), 0.f);
        float h1 = fmaxf(fmaf(v.y, s1.x, s1.y), 0.f);
        float h2v = fmaxf(fmaf(v.z, s2.x, s2.y), 0.f);
        float h3 = fmaxf(fmaf(v.w, s3.x, s3.y), 0.f);
        __half2 p0 = __floats2half2_rn(h0, h1), p1 = __floats2half2_rn(h2v, h3);
        unsigned* dst = (unsigned*)&As[row * MPAD + k];
        dst[0] = *(unsigned*)&p0;
        dst[1] = *(unsigned*)&p1;
    }
    __syncthreads();

    int wid = tid >> 5, lane = tid & 31;
    int r0 = wid * 16 + (lane >> 2);
    int kp = (lane & 3) * 2;

    float c[8][4];
#pragma unroll
    for (int nt = 0; nt < 8; nt++)
#pragma unroll
        for (int j = 0; j < 4; j++) c[nt][j] = 0.f;

#pragma unroll
    for (int kt = 0; kt < 4; kt++) {
        int kb = kt * 16 + kp;
        unsigned a0 = *(unsigned*)&As[r0 * MPAD + kb];
        unsigned a1 = *(unsigned*)&As[(r0 + 8) * MPAD + kb];
        unsigned a2 = *(unsigned*)&As[r0 * MPAD + kb + 8];
        unsigned a3 = *(unsigned*)&As[(r0 + 8) * MPAD + kb + 8];
#pragma unroll
        for (int nt = 0; nt < 8; nt++) {
            int n = nt * 8 + (lane >> 2);
            unsigned b0 = *(unsigned*)&Bs[n * MPAD + kb];
            unsigned b1 = *(unsigned*)&Bs[n * MPAD + kb + 8];
            mma16816(c[nt], a0, a1, a2, a3, b0, b1);
        }
    }

    int colp = (lane & 3) * 2;
#pragma unroll
    for (int rr = 0; rr < 2; rr++) {
        int node = nbase + r0 + rr * 8;
        if (node >= n_nodes) continue;
        __half* hrow = (__half*)(hh + (size_t)node * 16);
        float*  prow = pool + (size_t)__ldg(batch + node) * 192 + pool_off;
#pragma unroll
        for (int nt = 0; nt < 8; nt++) {
            int cA = nt * 8 + colp;
            float v0 = fmaxf(c[nt][rr * 2 + 0] + __ldg(b2 + cA), 0.f);
            float v1 = fmaxf(c[nt][rr * 2 + 1] + __ldg(b2 + cA + 1), 0.f);
            __half2 hv = __floats2half2_rn(v0, v1);
            *(unsigned*)&hrow[cA] = *(unsigned*)&hv;
            asm volatile("red.global.add.v2.f32 [%0], {%1,%2};"
                         :: "l"(prow + cA), "f"(v0), "f"(v1) : "memory");
        }
    }
}

// ---------------------------------------------------------------------------
// mlp64_hmma (layers 2/3): h = relu( relu(BN(zh@w1+b1)) @ w2 + b2 ).
// zh fp16 -> A-tile load is a raw uint4 copy. GEMM1 -> BN on frags -> As
// (warp-private rows) -> Bs := w2 -> GEMM2 -> epilogue.
// ---------------------------------------------------------------------------
__global__ __launch_bounds__(256) void mlp64_hmma_kernel(
    const uint2* __restrict__ zh,
    const float* __restrict__ w1, const float* __restrict__ b1,
    const float* __restrict__ gg, const float* __restrict__ bt,
    const float* __restrict__ rm, const float* __restrict__ rv,
    const float* __restrict__ w2, const float* __restrict__ b2,
    uint2*       __restrict__ hh,
    const int*   __restrict__ batch,
    float*       __restrict__ pool, int pool_off, int n_nodes)
{
    __shared__ __half As[128 * MPAD];
    __shared__ __half Bs[64 * MPAD];
    __shared__ float2 scsh[64];
    int tid = threadIdx.x;
    int nbase = blockIdx.x * 128;

    if (tid < 64) {
        float sc = __ldg(gg + tid) * rsqrtf(__ldg(rv + tid) + 1e-5f);
        float sh = (__ldg(b1 + tid) - __ldg(rm + tid)) * sc + __ldg(bt + tid);
        scsh[tid] = make_float2(sc, sh);
    }
    for (int i = tid; i < 64 * 64; i += 256) {
        int k = i >> 6, n = i & 63;
        Bs[n * MPAD + k] = __float2half(__ldg(w1 + i));
    }
    // raw fp16 copy: 128 rows x 8 uint4 (16B) each
    for (int i = tid; i < 1024; i += 256) {
        int row = i >> 3, q4 = i & 7;
        int gn = nbase + row; if (gn >= n_nodes) gn = n_nodes - 1;
        uint4 v = __ldg((const uint4*)(zh + (size_t)gn * 16) + q4);
        *(uint4*)&As[row * MPAD + q4 * 8] = v;
    }
    __syncthreads();

    int wid = tid >> 5, lane = tid & 31;
    int r0 = wid * 16 + (lane >> 2);
    int kp = (lane & 3) * 2;
    int colp = (lane & 3) * 2;

    // ---- GEMM1 (w1) ----
    float c[8][4];
#pragma unroll
    for (int nt = 0; nt < 8; nt++)
#pragma unroll
        for (int j = 0; j < 4; j++) c[nt][j] = 0.f;

#pragma unroll
    for (int kt = 0; kt < 4; kt++) {
        int kb = kt * 16 + kp;
        unsigned a0 = *(unsigned*)&As[r0 * MPAD + kb];
        unsigned a1 = *(unsigned*)&As[(r0 + 8) * MPAD + kb];
        unsigned a2 = *(unsigned*)&As[r0 * MPAD + kb + 8];
        unsigned a3 = *(unsigned*)&As[(r0 + 8) * MPAD + kb + 8];
#pragma unroll
        for (int nt = 0; nt < 8; nt++) {
            int n = nt * 8 + (lane >> 2);
            unsigned b0 = *(unsigned*)&Bs[n * MPAD + kb];
            unsigned b1 = *(unsigned*)&Bs[n * MPAD + kb + 8];
            mma16816(c[nt], a0, a1, a2, a3, b0, b1);
        }
    }

    // ---- BN + ReLU on fragments -> write h back into As (own rows only) ----
#pragma unroll
    for (int nt = 0; nt < 8; nt++) {
        int cA = nt * 8 + colp, cB = cA + 1;
        float2 sA = scsh[cA], sB = scsh[cB];
        float h00 = fmaxf(fmaf(c[nt][0], sA.x, sA.y), 0.f);
        float h01 = fmaxf(fmaf(c[nt][1], sB.x, sB.y), 0.f);
        float h10 = fmaxf(fmaf(c[nt][2], sA.x, sA.y), 0.f);
        float h11 = fmaxf(fmaf(c[nt][3], sB.x, sB.y), 0.f);
        __half2 p0 = __floats2half2_rn(h00, h01);
        __half2 p1 = __floats2half2_rn(h10, h11);
        *(unsigned*)&As[r0 * MPAD + cA]       = *(unsigned*)&p0;
        *(unsigned*)&As[(r0 + 8) * MPAD + cA] = *(unsigned*)&p1;
    }
    __syncthreads();   // all warps done reading Bs(w1) + writing their As rows

    for (int i = tid; i < 64 * 64; i += 256) {
        int k = i >> 6, n = i & 63;
        Bs[n * MPAD + k] = __float2half(__ldg(w2 + i));
    }
    __syncthreads();

    // ---- GEMM2 (w2) ----
#pragma unroll
    for (int nt = 0; nt < 8; nt++)
#pragma unroll
        for (int j = 0; j < 4; j++) c[nt][j] = 0.f;

#pragma unroll
    for (int kt = 0; kt < 4; kt++) {
        int kb = kt * 16 + kp;
        unsigned a0 = *(unsigned*)&As[r0 * MPAD + kb];
        unsigned a1 = *(unsigned*)&As[(r0 + 8) * MPAD + kb];
        unsigned a2 = *(unsigned*)&As[r0 * MPAD + kb + 8];
        unsigned a3 = *(unsigned*)&As[(r0 + 8) * MPAD + kb + 8];
#pragma unroll
        for (int nt = 0; nt < 8; nt++) {
            int n = nt * 8 + (lane >> 2);
            unsigned b0 = *(unsigned*)&Bs[n * MPAD + kb];
            unsigned b1 = *(unsigned*)&Bs[n * MPAD + kb + 8];
            mma16816(c[nt], a0, a1, a2, a3, b0, b1);
        }
    }

    // ---- epilogue ----
#pragma unroll
    for (int rr = 0; rr < 2; rr++) {
        int node = nbase + r0 + rr * 8;
        if (node >= n_nodes) continue;
        __half* hrow = (__half*)(hh + (size_t)node * 16);
        float*  prow = pool + (size_t)__ldg(batch + node) * 192 + pool_off;
#pragma unroll
        for (int nt = 0; nt < 8; nt++) {
            int cA = nt * 8 + colp;
            float v0 = fmaxf(c[nt][rr * 2 + 0] + __ldg(b2 + cA), 0.f);
            float v1 = fmaxf(c[nt][rr * 2 + 1] + __ldg(b2 + cA + 1), 0.f);
            __half2 hv = __floats2half2_rn(v0, v1);
            *(unsigned*)&hrow[cA] = *(unsigned*)&hv;
            asm volatile("red.global.add.v2.f32 [%0], {%1,%2};"
                         :: "l"(prow + cA), "f"(v0), "f"(v1) : "memory");
        }
    }
}

// ---------------------------------------------------------------------------
__global__ void final_kernel(const float* __restrict__ pool,
                             const float* __restrict__ lw1, const float* __restrict__ lb1,
                             const float* __restrict__ lw2, const float* __restrict__ lb2,
                             float* __restrict__ out)
{
    __shared__ float prow[192];
    __shared__ float hid[64];
    __shared__ float zz[2];
    int g = blockIdx.x, j = threadIdx.x;
    for (int k = j; k < 192; k += 64) prow[k] = pool[g * 192 + k];
    __syncthreads();
    float a = __ldg(lb1 + j);
    for (int k = 0; k < 192; k++) a = fmaf(prow[k], __ldg(lw1 + k * 64 + j), a);
    hid[j] = fmaxf(a, 0.f);
    __syncthreads();
    if (j < 2) {
        float zv = __ldg(lb2 + j);
#pragma unroll 8
        for (int k = 0; k < 64; k++) zv = fmaf(hid[k], __ldg(lw2 + k * 2 + j), zv);
        zz[j] = zv;
    }
    __syncthreads();
    if (j == 0) {
        float m   = fmaxf(zz[0], zz[1]);
        float lse = m + logf(expf(zz[0] - m) + expf(zz[1] - m));
        out[g * 2 + 0] = zz[0] - lse;
        out[g * 2 + 1] = zz[1] - lse;
    }
}

// ---------------------------------------------------------------------------
extern "C" void kernel_launch(void* const* d_in, const int* in_sizes, int n_in,
                              void* d_out, int out_size)
{
    const float* x     = (const float*)d_in[0];
    const int*   ei    = (const int*)  d_in[1];
    const int*   batch = (const int*)  d_in[2];

    int wi = (in_sizes[3] < 64) ? 4 : 3;
    const float* W[28];
    for (int i = 0; i < 28 && wi + i < n_in; i++) W[i] = (const float*)d_in[wi + i];

    int n_nodes = in_sizes[0] / 128;
    int n_edges = in_sizes[1] / 2;

    float *pool;
    uint2 *hh, *zh;
    int *deg, *row, *cur, *col, *bsum;
    cudaGetSymbolAddress((void**)&zh,   g_zh);
    cudaGetSymbolAddress((void**)&hh,   g_hh);
    cudaGetSymbolAddress((void**)&pool, g_pool);
    cudaGetSymbolAddress((void**)&deg,  g_deg);
    cudaGetSymbolAddress((void**)&row,  g_row);
    cudaGetSymbolAddress((void**)&cur,  g_cur);
    cudaGetSymbolAddress((void**)&col,  g_col);
    cudaGetSymbolAddress((void**)&bsum, g_bsum);

    float* out = (float*)d_out;

    const int SM_GA = (128 * APAD + 64 * BPAD) * 2;   // ~52KB dyn smem (gemmA)
    cudaFuncSetAttribute(gemmA_hmma_kernel,
                         cudaFuncAttributeMaxDynamicSharedMemorySize, SM_GA);

    int mlpBlocks  = (n_nodes + 127) / 128;
    int pullBlocks = (n_nodes * 16 + 255) / 256;
    int scanBlocks = (n_nodes + SCAN_B - 1) / SCAN_B;
    int zeroN      = n_nodes + 1;

    // ---- CSR build; gemmA_hmma is OUR launch #4 (profiled) ----
    zero_both_kernel<<<(zeroN + 255) / 256, 256>>>(deg, zeroN, pool, NGRAPH * 192); // 1
    hist_kernel<<<(n_edges + 255) / 256, 256>>>(ei, deg, n_edges);                  // 2
    bsum_kernel<<<scanBlocks, SCAN_B>>>(deg, bsum, n_nodes);                        // 3
    gemmA_hmma_kernel<<<mlpBlocks, 256, SM_GA>>>(x, W[0], hh, n_nodes);             // 4
    scatter_scan_kernel<<<scanBlocks, SCAN_B>>>(deg, bsum, row, cur, n_nodes);      // 5
    fill_kernel<<<(n_edges + 255) / 256, 256>>>(ei, cur, col, n_edges);             // 6

    // ---- layer 1 ----
    pull64h_kernel<<<pullBlocks, 256>>>(hh, row, col, zh, n_nodes);                 // 7
    mlpB_hmma_kernel<<<mlpBlocks, 256>>>(zh, W[1], W[2], W[3], W[4], W[5], W[6], W[7],
                                         hh, batch, pool, 0, n_nodes);              // 8

    // ---- layer 2 ----
    pull64h_kernel<<<pullBlocks, 256>>>(hh, row, col, zh, n_nodes);                 // 9
    mlp64_hmma_kernel<<<mlpBlocks, 256>>>(zh, W[8], W[9], W[10], W[11], W[12], W[13], W[14], W[15],
                                          hh, batch, pool, 64, n_nodes);            // 10

    // ---- layer 3 ----
    pull64h_kernel<<<pullBlocks, 256>>>(hh, row, col, zh, n_nodes);                 // 11
    mlp64_hmma_kernel<<<mlpBlocks, 256>>>(zh, W[16], W[17], W[18], W[19], W[20], W[21], W[22], W[23],
                                          hh, batch, pool, 128, n_nodes);           // 12

    final_kernel<<<NGRAPH, 64>>>(pool, W[24], W[25], W[26], W[27], out);            // 13
}